// round 13
// baseline (speedup 1.0000x reference)
#include <cuda_runtime.h>
#include <cuda_fp16.h>

typedef unsigned long long u64;

// Problem constants
#define BB 4
#define CC 32
#define DW 64
#define HH 256
#define WW 256
#define HW 65536

// Scratch (device globals: allocation-free rule). fp16 intermediates.
__device__ __half g_t[BB * DW * HW];    // conv1(LN(inp)) output, 32 MB
__device__ __half g_xsg[BB * CC * HW];  // gate output, 16 MB
__device__ float g_part[BB * CC * 64];  // per-(b,ch,tile) partial sums
__device__ float g_s[BB * CC];          // SCA scale per (b,ch)

// ---- packed fp32x2 helpers (sm_100+) ----
__device__ __forceinline__ u64 pack2(float lo, float hi) {
    u64 r;
    asm("mov.b64 %0, {%1,%2};" : "=l"(r) : "f"(lo), "f"(hi));
    return r;
}
__device__ __forceinline__ float2 unpack2(u64 v) {
    float lo, hi;
    asm("mov.b64 {%0,%1}, %2;" : "=f"(lo), "=f"(hi) : "l"(v));
    return make_float2(lo, hi);
}
__device__ __forceinline__ u64 ffma2(u64 a, u64 b, u64 c) {
    u64 d;
    asm("fma.rn.f32x2 %0, %1, %2, %3;" : "=l"(d) : "l"(a), "l"(b), "l"(c));
    return d;
}
__device__ __forceinline__ u64 add2(u64 a, u64 b) {
    u64 d;
    asm("add.rn.f32x2 %0, %1, %2;" : "=l"(d) : "l"(a), "l"(b));
    return d;
}
__device__ __forceinline__ u64 mul2(u64 a, u64 b) {
    u64 d;
    asm("mul.rn.f32x2 %0, %1, %2;" : "=l"(d) : "l"(a), "l"(b));
    return d;
}
__device__ __forceinline__ float hsum2(u64 v) {
    float2 f = unpack2(v);
    return f.x + f.y;
}
__device__ __forceinline__ float hsum2h(__half2 v) {
    float2 f = __half22float2(v);
    return f.x + f.y;
}

// =====================================================================
// K1: LayerNorm + conv1 (32 -> 64), pixel-pair, PERSISTENT 2-CHUNK:
// grid 512 (single wave), weights staged once, loop over 2x256 pixels.
// =====================================================================
__global__ __launch_bounds__(128) void k1(const float* __restrict__ inp,
                                          const float* __restrict__ w1,
                                          const float* __restrict__ b1g,
                                          const float* __restrict__ n1w,
                                          const float* __restrict__ n1b) {
    __shared__ __align__(16) __half2 w1h[64 * 16];  // [o][c2] channel pairs
    __shared__ float snw[32], snb[32], sb64[64];
    int tid = threadIdx.x;
    for (int i = tid; i < 1024; i += 128) {
        int o = i >> 4, c2 = i & 15;
        w1h[i] = __floats2half2_rn(w1[o * 32 + 2 * c2], w1[o * 32 + 2 * c2 + 1]);
    }
    if (tid < 32) { snw[tid] = n1w[tid]; snb[tid] = n1b[tid]; }
    if (tid < 64) sb64[tid] = b1g[tid];
    __syncthreads();

    int b = blockIdx.x >> 7;  // 512 | 65536: batch constant per block

#pragma unroll 1
    for (int it = 0; it < 2; it++) {
        int p = blockIdx.x * 512 + it * 256 + tid * 2;
        int pix = p & 65535;
        const float* ip = inp + b * CC * HW + pix;

        u64 xv[32];
        u64 sa = 0ull, qa = 0ull;
#pragma unroll
        for (int c = 0; c < 32; c++) {
            float2 v = *(const float2*)&ip[c * HW];
            u64 t = pack2(v.x, v.y);
            xv[c] = t;
            sa = add2(sa, t);
            qa = ffma2(t, t, qa);
        }
        u64 nmu = mul2(sa, pack2(-1.f / 32.f, -1.f / 32.f));
        float2 qf = unpack2(qa);
        float2 nm = unpack2(nmu);
        float var0 = qf.x * (1.f / 32.f) - nm.x * nm.x;
        float var1 = qf.y * (1.f / 32.f) - nm.y * nm.y;
        u64 rs2 = pack2(rsqrtf(var0 + 1e-6f), rsqrtf(var1 + 1e-6f));

        __half2 xh0[16], xh1[16];
#pragma unroll
        for (int c2 = 0; c2 < 16; c2++) {
            int ca = 2 * c2, cb = 2 * c2 + 1;
            u64 ta = mul2(add2(xv[ca], nmu), rs2);
            u64 tb = mul2(add2(xv[cb], nmu), rs2);
            u64 za = ffma2(ta, pack2(snw[ca], snw[ca]), pack2(snb[ca], snb[ca]));
            u64 zb = ffma2(tb, pack2(snw[cb], snw[cb]), pack2(snb[cb], snb[cb]));
            float2 fa = unpack2(za), fb = unpack2(zb);
            xh0[c2] = __floats2half2_rn(fa.x, fb.x);
            xh1[c2] = __floats2half2_rn(fa.y, fb.y);
        }

        __half* op = g_t + b * DW * HW + pix;
#pragma unroll 4
        for (int o = 0; o < 64; o++) {
            __half2 a0 = __floats2half2_rn(0.f, 0.f);
            __half2 a1 = a0;
            const __half2* wr = &w1h[o * 16];
#pragma unroll
            for (int c2 = 0; c2 < 16; c2++) {
                __half2 w = wr[c2];
                a0 = __hfma2(w, xh0[c2], a0);
                a1 = __hfma2(w, xh1[c2], a1);
            }
            float r0 = sb64[o] + hsum2h(a0);
            float r1 = sb64[o] + hsum2h(a1);
            *(__half2*)&op[o * HW] = __floats2half2_rn(r0, r1);
        }
    }
}

// =====================================================================
// K2: DDF + SimpleGate + SCA partials — HALF2-LANE (frozen from R11).
// =====================================================================
__global__ __launch_bounds__(128) void k2(const float* __restrict__ w2g) {
    int tile = blockIdx.x;  // 0..63
    int chp = blockIdx.y;   // 0..31
    int b = blockIdx.z;
    int tyi = tile >> 3, txi = tile & 7;
    int h0 = tyi * 32, w0 = txi * 32;
    const int TSTR = 35;  // smem row stride in half2 elems

    __shared__ __align__(16) __half2 tin[34 * TSTR];  // (ch0, ch1) per px
    __shared__ __align__(16) __half2 Wc[9][36];       // (ch0, ch1) per wgt
    __shared__ float red[4];

    int tid = threadIdx.x;

    {
        const __half* src0 = g_t + (b * DW + chp) * HW;
        const __half* src1 = g_t + (b * DW + chp + 32) * HW;
        __half hz = __float2half_rn(0.f);
        for (int idx = tid; idx < 34 * 34; idx += 128) {
            int r = idx / 34, c = idx - r * 34;
            int gh = h0 - 1 + r, gw = w0 - 1 + c;
            __half v0 = hz, v1 = hz;
            if ((unsigned)gh < 256u && (unsigned)gw < 256u) {
                int off = gh * 256 + gw;
                v0 = src0[off];
                v1 = src1[off];
            }
            tin[r * TSTR + c] = __halves2half2(v0, v1);
        }
    }
    {
        int ybase = 4 * tyi - 1, xbase = 4 * txi - 1;
        for (int idx = tid; idx < 324; idx += 128) {
            int t = idx / 36;
            int rc = idx - t * 36;
            int rr = rc / 6, cj = rc - rr * 6;
            int ys = min(max(ybase + rr, 0), 31);
            int xs = min(max(xbase + cj, 0), 31);
            float wv0 = w2g[(((b * 64 + chp) * 9 + t) * 32 + ys) * 32 + xs];
            float wv1 = w2g[(((b * 64 + chp + 32) * 9 + t) * 32 + ys) * 32 + xs];
            Wc[t][rc] = __floats2half2_rn(wv0, wv1);
        }
    }
    __syncthreads();

    int row = tid >> 2;        // 0..31
    int seg = (tid & 3) * 8;   // 0,8,16,24
    int h = h0 + row;

    float srcy = (h - 3.5f) * 0.125f;
    float y0f = floorf(srcy);
    float fy = srcy - y0f;
    int y0 = (int)y0f;
    int ybase = 4 * tyi - 1;
    int y0l = max(y0, 0) - ybase;
    int y1l = min(y0 + 1, 31) - ybase;

    int m = 4 * txi + (seg >> 3);
    int xbase = 4 * txi - 1;
    int a0 = max(m - 1, 0) - xbase;
    int a1 = m - xbase;
    int b1i = min(m + 1, 31) - xbase;

    __half2 fy2 = __float2half2_rn(fy);
    const __half2 K0 = __float2half2_rn(0.5625f);
    const __half2 K1 = __float2half2_rn(0.6875f);
    const __half2 K2 = __float2half2_rn(0.8125f);
    const __half2 K3 = __float2half2_rn(0.9375f);
    const __half2 K4 = __float2half2_rn(0.0625f);
    const __half2 K5 = __float2half2_rn(0.1875f);
    const __half2 K6 = __float2half2_rn(0.3125f);
    const __half2 K7 = __float2half2_rn(0.4375f);

    __half2 ra[10], rb[10], rcr[10];
#pragma unroll
    for (int k = 0; k < 10; k++) {
        ra[k] = tin[row * TSTR + seg + k];
        rb[k] = tin[(row + 1) * TSTR + seg + k];
        rcr[k] = tin[(row + 2) * TSTR + seg + k];
    }

    __half2 acc[8];
#pragma unroll
    for (int i = 0; i < 8; i++) acc[i] = __floats2half2_rn(0.f, 0.f);

#define TAP(RR, T, DX)                                                    \
    {                                                                     \
        const __half2* Wp = Wc[T];                                        \
        __half2 v0a = Wp[y0l * 6 + a0], v0b = Wp[y1l * 6 + a0];           \
        __half2 v1a = Wp[y0l * 6 + a1], v1b = Wp[y1l * 6 + a1];           \
        __half2 v2a = Wp[y0l * 6 + b1i], v2b = Wp[y1l * 6 + b1i];         \
        __half2 v0 = __hfma2(fy2, __hsub2(v0b, v0a), v0a);                \
        __half2 v1 = __hfma2(fy2, __hsub2(v1b, v1a), v1a);                \
        __half2 v2 = __hfma2(fy2, __hsub2(v2b, v2a), v2a);                \
        __half2 dA = __hsub2(v1, v0), dB = __hsub2(v2, v1);               \
        acc[0] = __hfma2(__hfma2(K0, dA, v0), RR[0 + DX], acc[0]);        \
        acc[1] = __hfma2(__hfma2(K1, dA, v0), RR[1 + DX], acc[1]);        \
        acc[2] = __hfma2(__hfma2(K2, dA, v0), RR[2 + DX], acc[2]);        \
        acc[3] = __hfma2(__hfma2(K3, dA, v0), RR[3 + DX], acc[3]);        \
        acc[4] = __hfma2(__hfma2(K4, dB, v1), RR[4 + DX], acc[4]);        \
        acc[5] = __hfma2(__hfma2(K5, dB, v1), RR[5 + DX], acc[5]);        \
        acc[6] = __hfma2(__hfma2(K6, dB, v1), RR[6 + DX], acc[6]);        \
        acc[7] = __hfma2(__hfma2(K7, dB, v1), RR[7 + DX], acc[7]);        \
    }
    TAP(ra, 0, 0) TAP(ra, 1, 1) TAP(ra, 2, 2)
    TAP(rb, 3, 0) TAP(rb, 4, 1) TAP(rb, 5, 2)
    TAP(rcr, 6, 0) TAP(rcr, 7, 1) TAP(rcr, 8, 2)
#undef TAP

    float g[8];
    float tsum = 0.f;
#pragma unroll
    for (int i = 0; i < 8; i++) {
        float2 f = __half22float2(acc[i]);
        g[i] = f.x * f.y;
        tsum += g[i];
    }
    __half2* op =
        (__half2*)(g_xsg + (b * CC + chp) * HW + h * 256 + w0 + seg);
    op[0] = __floats2half2_rn(g[0], g[1]);
    op[1] = __floats2half2_rn(g[2], g[3]);
    op[2] = __floats2half2_rn(g[4], g[5]);
    op[3] = __floats2half2_rn(g[6], g[7]);

#pragma unroll
    for (int off = 16; off; off >>= 1)
        tsum += __shfl_xor_sync(0xffffffffu, tsum, off);
    if ((tid & 31) == 0) red[tid >> 5] = tsum;
    __syncthreads();
    if (tid == 0)
        g_part[(b * CC + chp) * 64 + tile] = red[0] + red[1] + red[2] + red[3];
}

// =====================================================================
// K3: deterministic reduction of partials + SCA 1x1 conv -> g_s
// =====================================================================
__global__ void k3(const float* __restrict__ sw, const float* __restrict__ sbias) {
    __shared__ float mean_sm[128];
    int tid = threadIdx.x;  // 128 = 4 batches x 32 channels
    int b = tid >> 5, c = tid & 31;
    float sum = 0.f;
    for (int t = 0; t < 64; t++) sum += g_part[(b * CC + c) * 64 + t];
    mean_sm[tid] = sum * (1.f / 65536.f);
    __syncthreads();
    float acc = sbias[c];
#pragma unroll
    for (int k = 0; k < 32; k++) acc += sw[c * 32 + k] * mean_sm[b * 32 + k];
    g_s[tid] = acc;
}

// =====================================================================
// K4: x*s -> conv3 -> y=inp+beta*x -> LN2 -> conv4 -> gate -> conv5
//     -> out. Pixel-pair + PERSISTENT 2-CHUNK: grid 512 (one wave),
// weights staged once, loop over 2x256 pixels.
// =====================================================================
__global__ __launch_bounds__(128) void k4(const float* __restrict__ inp,
                                          const float* __restrict__ w3,
                                          const float* __restrict__ b3g,
                                          const float* __restrict__ w4,
                                          const float* __restrict__ b4g,
                                          const float* __restrict__ w5,
                                          const float* __restrict__ b5g,
                                          const float* __restrict__ n2wg,
                                          const float* __restrict__ n2bg,
                                          const float* __restrict__ betag,
                                          const float* __restrict__ gammag,
                                          float* __restrict__ out) {
    __shared__ __align__(16) __half2 w3h[32 * 16];  // [o][c2] channel pairs
    __shared__ __align__(16) __half2 w4h[64 * 16];
    __shared__ __align__(16) __half2 w5h[32 * 16];
    __shared__ float sv[32], n2w[32], n2b[32], bet[32], gam[32];
    __shared__ float b3s[32], b4s[64], b5s[32];

    int tid = threadIdx.x;
    int b = blockIdx.x >> 7;  // 512 | 65536: batch constant per block

    for (int i = tid; i < 512; i += 128) {
        int o = i >> 4, c2 = i & 15;
        w3h[i] = __floats2half2_rn(w3[o * 32 + 2 * c2], w3[o * 32 + 2 * c2 + 1]);
        w5h[i] = __floats2half2_rn(w5[o * 32 + 2 * c2], w5[o * 32 + 2 * c2 + 1]);
    }
    for (int i = tid; i < 1024; i += 128) {
        int o = i >> 4, c2 = i & 15;
        w4h[i] = __floats2half2_rn(w4[o * 32 + 2 * c2], w4[o * 32 + 2 * c2 + 1]);
    }
    if (tid < 32) {
        sv[tid] = g_s[b * 32 + tid];
        n2w[tid] = n2wg[tid];
        n2b[tid] = n2bg[tid];
        bet[tid] = betag[tid];
        gam[tid] = gammag[tid];
        b3s[tid] = b3g[tid];
        b5s[tid] = b5g[tid];
    }
    if (tid < 64) b4s[tid] = b4g[tid];
    __syncthreads();

#pragma unroll 1
    for (int it = 0; it < 2; it++) {
        int p = blockIdx.x * 512 + it * 256 + tid * 2;
        int pix = p & 65535;

        // x = gate_out * s (fp16 half2 loads: lanes = pixels); repack to
        // channel-paired half2 per pixel.
        __half2 xh0[16], xh1[16];
        {
            const __half* xg = g_xsg + b * CC * HW + pix;
#pragma unroll
            for (int c2 = 0; c2 < 16; c2++) {
                float2 fa = __half22float2(*(const __half2*)&xg[(2 * c2) * HW]);
                float2 fb =
                    __half22float2(*(const __half2*)&xg[(2 * c2 + 1) * HW]);
                float s0 = sv[2 * c2], s1 = sv[2 * c2 + 1];
                xh0[c2] = __floats2half2_rn(fa.x * s0, fb.x * s1);  // pixel 0
                xh1[c2] = __floats2half2_rn(fa.y * s0, fb.y * s1);  // pixel 1
            }
        }

        // ---- conv3 (HFMA2, weights shared across pixels) + residual ----
        u64 yp0[16], yp1[16];  // channel pairs per pixel (fp32)
        const float* ip = inp + b * CC * HW + pix;
#pragma unroll 2
        for (int j = 0; j < 16; j++) {
            __half2 z = __floats2half2_rn(0.f, 0.f);
            __half2 a00 = z, a10 = z, a01 = z, a11 = z;
            const __half2* wr0 = &w3h[(2 * j) * 16];
            const __half2* wr1 = &w3h[(2 * j + 1) * 16];
#pragma unroll
            for (int c2 = 0; c2 < 16; c2++) {
                __half2 w0 = wr0[c2], w1 = wr1[c2];
                a00 = __hfma2(w0, xh0[c2], a00);
                a01 = __hfma2(w0, xh1[c2], a01);
                a10 = __hfma2(w1, xh0[c2], a10);
                a11 = __hfma2(w1, xh1[c2], a11);
            }
            float2 i0 = *(const float2*)&ip[(2 * j) * HW];  // (p0,p1)
            float2 i1 = *(const float2*)&ip[(2 * j + 1) * HW];
            float bt0 = bet[2 * j], bt1 = bet[2 * j + 1];
            float bb0 = b3s[2 * j], bb1 = b3s[2 * j + 1];
            yp0[j] = pack2(i0.x + bt0 * (bb0 + hsum2h(a00)),
                           i1.x + bt1 * (bb1 + hsum2h(a10)));
            yp1[j] = pack2(i0.y + bt0 * (bb0 + hsum2h(a01)),
                           i1.y + bt1 * (bb1 + hsum2h(a11)));
        }

        // ---- LN2 per pixel -> zh (reuse xh regs) ----
        {
            u64 sa0 = 0ull, qa0 = 0ull, sa1 = 0ull, qa1 = 0ull;
#pragma unroll
            for (int j = 0; j < 16; j++) {
                sa0 = add2(sa0, yp0[j]);
                qa0 = ffma2(yp0[j], yp0[j], qa0);
                sa1 = add2(sa1, yp1[j]);
                qa1 = ffma2(yp1[j], yp1[j], qa1);
            }
            float s0 = hsum2(sa0), q0 = hsum2(qa0);
            float s1 = hsum2(sa1), q1 = hsum2(qa1);
            float mu0 = s0 * (1.f / 32.f);
            float mu1 = s1 * (1.f / 32.f);
            float rstd0 = rsqrtf(q0 * (1.f / 32.f) - mu0 * mu0 + 1e-6f);
            float rstd1 = rsqrtf(q1 * (1.f / 32.f) - mu1 * mu1 + 1e-6f);
#pragma unroll
            for (int j = 0; j < 16; j++) {
                float w0 = n2w[2 * j], w1 = n2w[2 * j + 1];
                float c0 = n2b[2 * j], c1 = n2b[2 * j + 1];
                float2 f0 = unpack2(yp0[j]);
                float2 f1 = unpack2(yp1[j]);
                xh0[j] = __floats2half2_rn((f0.x - mu0) * rstd0 * w0 + c0,
                                           (f0.y - mu0) * rstd0 * w1 + c1);
                xh1[j] = __floats2half2_rn((f1.x - mu1) * rstd1 * w0 + c0,
                                           (f1.y - mu1) * rstd1 * w1 + c1);
            }
        }

        // ---- conv4 (64 outs, HFMA2, shared weights) + gate -> gh ----
        __half2 gh0[16], gh1[16];
#pragma unroll 2
        for (int j = 0; j < 16; j++) {
            __half2 z = __floats2half2_rn(0.f, 0.f);
            __half2 aA0 = z, aB0 = z, aC0 = z, aD0 = z;
            __half2 aA1 = z, aB1 = z, aC1 = z, aD1 = z;
            const __half2* wA = &w4h[(2 * j) * 16];
            const __half2* wB = &w4h[(2 * j + 1) * 16];
            const __half2* wC = &w4h[(2 * j + 32) * 16];
            const __half2* wD = &w4h[(2 * j + 33) * 16];
#pragma unroll
            for (int c2 = 0; c2 < 16; c2++) {
                __half2 x0 = xh0[c2], x1 = xh1[c2];
                __half2 wa = wA[c2], wb = wB[c2], wc = wC[c2], wd = wD[c2];
                aA0 = __hfma2(wa, x0, aA0);
                aA1 = __hfma2(wa, x1, aA1);
                aB0 = __hfma2(wb, x0, aB0);
                aB1 = __hfma2(wb, x1, aB1);
                aC0 = __hfma2(wc, x0, aC0);
                aC1 = __hfma2(wc, x1, aC1);
                aD0 = __hfma2(wd, x0, aD0);
                aD1 = __hfma2(wd, x1, aD1);
            }
            float bA = b4s[2 * j], bB = b4s[2 * j + 1];
            float bC = b4s[2 * j + 32], bD = b4s[2 * j + 33];
            gh0[j] =
                __floats2half2_rn((bA + hsum2h(aA0)) * (bC + hsum2h(aC0)),
                                  (bB + hsum2h(aB0)) * (bD + hsum2h(aD0)));
            gh1[j] =
                __floats2half2_rn((bA + hsum2h(aA1)) * (bC + hsum2h(aC1)),
                                  (bB + hsum2h(aB1)) * (bD + hsum2h(aD1)));
        }

        // ---- conv5 (HFMA2, shared weights) + final residual ----
        float* op = out + b * CC * HW + pix;
#pragma unroll 2
        for (int j = 0; j < 16; j++) {
            __half2 z = __floats2half2_rn(0.f, 0.f);
            __half2 a00 = z, a10 = z, a01 = z, a11 = z;
            const __half2* wr0 = &w5h[(2 * j) * 16];
            const __half2* wr1 = &w5h[(2 * j + 1) * 16];
#pragma unroll
            for (int c2 = 0; c2 < 16; c2++) {
                __half2 w0 = wr0[c2], w1 = wr1[c2];
                a00 = __hfma2(w0, gh0[c2], a00);
                a01 = __hfma2(w0, gh1[c2], a01);
                a10 = __hfma2(w1, gh0[c2], a10);
                a11 = __hfma2(w1, gh1[c2], a11);
            }
            float gm0 = gam[2 * j], gm1 = gam[2 * j + 1];
            float bb0 = b5s[2 * j], bb1 = b5s[2 * j + 1];
            float2 f0 = unpack2(yp0[j]);  // (ch even, ch odd) pixel 0
            float2 f1 = unpack2(yp1[j]);  // pixel 1
            *(float2*)&op[(2 * j) * HW] =
                make_float2(f0.x + gm0 * (bb0 + hsum2h(a00)),
                            f1.x + gm0 * (bb0 + hsum2h(a01)));
            *(float2*)&op[(2 * j + 1) * HW] =
                make_float2(f0.y + gm1 * (bb1 + hsum2h(a10)),
                            f1.y + gm1 * (bb1 + hsum2h(a11)));
        }
    }
}

extern "C" void kernel_launch(void* const* d_in, const int* in_sizes, int n_in,
                              void* d_out, int out_size) {
    const float* inp     = (const float*)d_in[0];
    const float* w2      = (const float*)d_in[1];
    const float* conv1_w = (const float*)d_in[2];
    const float* conv1_b = (const float*)d_in[3];
    const float* conv3_w = (const float*)d_in[4];
    const float* conv3_b = (const float*)d_in[5];
    const float* sca_w   = (const float*)d_in[6];
    const float* sca_b   = (const float*)d_in[7];
    const float* conv4_w = (const float*)d_in[8];
    const float* conv4_b = (const float*)d_in[9];
    const float* conv5_w = (const float*)d_in[10];
    const float* conv5_b = (const float*)d_in[11];
    const float* norm1_w = (const float*)d_in[12];
    const float* norm1_b = (const float*)d_in[13];
    const float* norm2_w = (const float*)d_in[14];
    const float* norm2_b = (const float*)d_in[15];
    const float* beta    = (const float*)d_in[16];
    const float* gamma   = (const float*)d_in[17];
    float* out = (float*)d_out;

    k1<<<512, 128>>>(inp, conv1_w, conv1_b, norm1_w, norm1_b);
    k2<<<dim3(64, 32, 4), 128>>>(w2);
    k3<<<1, 128>>>(sca_w, sca_b);
    k4<<<512, 128>>>(inp, conv3_w, conv3_b, conv4_w, conv4_b, conv5_w, conv5_b,
                     norm2_w, norm2_b, beta, gamma, out);
}

// round 14
// speedup vs baseline: 1.2428x; 1.2428x over previous
#include <cuda_runtime.h>
#include <cuda_fp16.h>

typedef unsigned long long u64;

// Problem constants
#define BB 4
#define CC 32
#define DW 64
#define HH 256
#define WW 256
#define HW 65536

// Scratch (device globals: allocation-free rule). fp16 intermediates.
// g_tp: conv1 output in channel-pair-interleaved layout:
//   g_tp[(b*32 + o)*HW + pix] = (ch o, ch o+32) as half2.
__device__ __half2 g_tp[BB * 32 * HW];  // 32 MB
__device__ __half g_xsg[BB * CC * HW];  // gate output, 16 MB
__device__ float g_part[BB * CC * 64];  // per-(b,ch,tile) partial sums
__device__ float g_s[BB * CC];          // SCA scale per (b,ch)

// ---- packed fp32x2 helpers (sm_100+) ----
__device__ __forceinline__ u64 pack2(float lo, float hi) {
    u64 r;
    asm("mov.b64 %0, {%1,%2};" : "=l"(r) : "f"(lo), "f"(hi));
    return r;
}
__device__ __forceinline__ float2 unpack2(u64 v) {
    float lo, hi;
    asm("mov.b64 {%0,%1}, %2;" : "=f"(lo), "=f"(hi) : "l"(v));
    return make_float2(lo, hi);
}
__device__ __forceinline__ u64 ffma2(u64 a, u64 b, u64 c) {
    u64 d;
    asm("fma.rn.f32x2 %0, %1, %2, %3;" : "=l"(d) : "l"(a), "l"(b), "l"(c));
    return d;
}
__device__ __forceinline__ u64 add2(u64 a, u64 b) {
    u64 d;
    asm("add.rn.f32x2 %0, %1, %2;" : "=l"(d) : "l"(a), "l"(b));
    return d;
}
__device__ __forceinline__ u64 mul2(u64 a, u64 b) {
    u64 d;
    asm("mul.rn.f32x2 %0, %1, %2;" : "=l"(d) : "l"(a), "l"(b));
    return d;
}
__device__ __forceinline__ float hsum2(u64 v) {
    float2 f = unpack2(v);
    return f.x + f.y;
}
__device__ __forceinline__ float hsum2h(__half2 v) {
    float2 f = __half22float2(v);
    return f.x + f.y;
}

// =====================================================================
// K1: LayerNorm + conv1 (32 -> 64), pixel-pair (R12 structure), writing
// channel-pair-interleaved g_tp: one 8B store per output-pair/pixel-pair.
// =====================================================================
__global__ __launch_bounds__(128) void k1(const float* __restrict__ inp,
                                          const float* __restrict__ w1,
                                          const float* __restrict__ b1g,
                                          const float* __restrict__ n1w,
                                          const float* __restrict__ n1b) {
    __shared__ __align__(16) __half2 w1h[64 * 16];  // [o][c2] channel pairs
    __shared__ float snw[32], snb[32], sb64[64];
    int tid = threadIdx.x;
    for (int i = tid; i < 1024; i += 128) {
        int o = i >> 4, c2 = i & 15;
        w1h[i] = __floats2half2_rn(w1[o * 32 + 2 * c2], w1[o * 32 + 2 * c2 + 1]);
    }
    if (tid < 32) { snw[tid] = n1w[tid]; snb[tid] = n1b[tid]; }
    if (tid < 64) sb64[tid] = b1g[tid];
    __syncthreads();

    int p = blockIdx.x * 256 + tid * 2;  // 2 pixels per thread
    int b = p >> 16, pix = p & 65535;
    const float* ip = inp + b * CC * HW + pix;

    u64 xv[32];
    u64 sa = 0ull, qa = 0ull;
#pragma unroll
    for (int c = 0; c < 32; c++) {
        float2 v = *(const float2*)&ip[c * HW];
        u64 t = pack2(v.x, v.y);
        xv[c] = t;
        sa = add2(sa, t);
        qa = ffma2(t, t, qa);
    }
    u64 nmu = mul2(sa, pack2(-1.f / 32.f, -1.f / 32.f));
    float2 qf = unpack2(qa);
    float2 nm = unpack2(nmu);
    float var0 = qf.x * (1.f / 32.f) - nm.x * nm.x;
    float var1 = qf.y * (1.f / 32.f) - nm.y * nm.y;
    u64 rs2 = pack2(rsqrtf(var0 + 1e-6f), rsqrtf(var1 + 1e-6f));

    __half2 xh0[16], xh1[16];
#pragma unroll
    for (int c2 = 0; c2 < 16; c2++) {
        int ca = 2 * c2, cb = 2 * c2 + 1;
        u64 ta = mul2(add2(xv[ca], nmu), rs2);
        u64 tb = mul2(add2(xv[cb], nmu), rs2);
        u64 za = ffma2(ta, pack2(snw[ca], snw[ca]), pack2(snb[ca], snb[ca]));
        u64 zb = ffma2(tb, pack2(snw[cb], snw[cb]), pack2(snb[cb], snb[cb]));
        float2 fa = unpack2(za), fb = unpack2(zb);
        xh0[c2] = __floats2half2_rn(fa.x, fb.x);
        xh1[c2] = __floats2half2_rn(fa.y, fb.y);
    }

    __half2* op = g_tp + b * 32 * HW + pix;
#pragma unroll 2
    for (int o = 0; o < 32; o++) {
        __half2 z = __floats2half2_rn(0.f, 0.f);
        __half2 aL0 = z, aL1 = z, aH0 = z, aH1 = z;
        const __half2* wrL = &w1h[o * 16];
        const __half2* wrH = &w1h[(o + 32) * 16];
#pragma unroll
        for (int c2 = 0; c2 < 16; c2++) {
            __half2 x0 = xh0[c2], x1 = xh1[c2];
            aL0 = __hfma2(wrL[c2], x0, aL0);
            aL1 = __hfma2(wrL[c2], x1, aL1);
            aH0 = __hfma2(wrH[c2], x0, aH0);
            aH1 = __hfma2(wrH[c2], x1, aH1);
        }
        float bL = sb64[o], bH = sb64[o + 32];
        __half2 p0 = __floats2half2_rn(bL + hsum2h(aL0), bH + hsum2h(aH0));
        __half2 p1 = __floats2half2_rn(bL + hsum2h(aL1), bH + hsum2h(aH1));
        __half2* dst = op + o * HW;  // pix even -> 8B-aligned pair
        dst[0] = p0;
        dst[1] = p1;
    }
}

// =====================================================================
// K2: DDF + SimpleGate + SCA partials — HALF2-LANE; tin staging now one
// aligned 4B LDG per pixel from channel-pair-interleaved g_tp.
// =====================================================================
__global__ __launch_bounds__(128) void k2(const float* __restrict__ w2g) {
    int tile = blockIdx.x;  // 0..63
    int chp = blockIdx.y;   // 0..31
    int b = blockIdx.z;
    int tyi = tile >> 3, txi = tile & 7;
    int h0 = tyi * 32, w0 = txi * 32;
    const int TSTR = 35;  // smem row stride in half2 elems

    __shared__ __align__(16) __half2 tin[34 * TSTR];  // (ch0, ch1) per px
    __shared__ __align__(16) __half2 Wc[9][36];       // (ch0, ch1) per wgt
    __shared__ float red[4];

    int tid = threadIdx.x;

    {
        const __half2* src = g_tp + (b * 32 + chp) * HW;
        __half2 hz = __floats2half2_rn(0.f, 0.f);
        for (int idx = tid; idx < 34 * 34; idx += 128) {
            int r = idx / 34, c = idx - r * 34;
            int gh = h0 - 1 + r, gw = w0 - 1 + c;
            __half2 v = hz;
            if ((unsigned)gh < 256u && (unsigned)gw < 256u)
                v = src[gh * 256 + gw];
            tin[r * TSTR + c] = v;
        }
    }
    {
        int ybase = 4 * tyi - 1, xbase = 4 * txi - 1;
        for (int idx = tid; idx < 324; idx += 128) {
            int t = idx / 36;
            int rc = idx - t * 36;
            int rr = rc / 6, cj = rc - rr * 6;
            int ys = min(max(ybase + rr, 0), 31);
            int xs = min(max(xbase + cj, 0), 31);
            float wv0 = w2g[(((b * 64 + chp) * 9 + t) * 32 + ys) * 32 + xs];
            float wv1 = w2g[(((b * 64 + chp + 32) * 9 + t) * 32 + ys) * 32 + xs];
            Wc[t][rc] = __floats2half2_rn(wv0, wv1);
        }
    }
    __syncthreads();

    int row = tid >> 2;        // 0..31
    int seg = (tid & 3) * 8;   // 0,8,16,24
    int h = h0 + row;

    float srcy = (h - 3.5f) * 0.125f;
    float y0f = floorf(srcy);
    float fy = srcy - y0f;
    int y0 = (int)y0f;
    int ybase = 4 * tyi - 1;
    int y0l = max(y0, 0) - ybase;
    int y1l = min(y0 + 1, 31) - ybase;

    int m = 4 * txi + (seg >> 3);
    int xbase = 4 * txi - 1;
    int a0 = max(m - 1, 0) - xbase;
    int a1 = m - xbase;
    int b1i = min(m + 1, 31) - xbase;

    __half2 fy2 = __float2half2_rn(fy);
    const __half2 K0 = __float2half2_rn(0.5625f);
    const __half2 K1 = __float2half2_rn(0.6875f);
    const __half2 K2 = __float2half2_rn(0.8125f);
    const __half2 K3 = __float2half2_rn(0.9375f);
    const __half2 K4 = __float2half2_rn(0.0625f);
    const __half2 K5 = __float2half2_rn(0.1875f);
    const __half2 K6 = __float2half2_rn(0.3125f);
    const __half2 K7 = __float2half2_rn(0.4375f);

    __half2 ra[10], rb[10], rcr[10];
#pragma unroll
    for (int k = 0; k < 10; k++) {
        ra[k] = tin[row * TSTR + seg + k];
        rb[k] = tin[(row + 1) * TSTR + seg + k];
        rcr[k] = tin[(row + 2) * TSTR + seg + k];
    }

    __half2 acc[8];
#pragma unroll
    for (int i = 0; i < 8; i++) acc[i] = __floats2half2_rn(0.f, 0.f);

#define TAP(RR, T, DX)                                                    \
    {                                                                     \
        const __half2* Wp = Wc[T];                                        \
        __half2 v0a = Wp[y0l * 6 + a0], v0b = Wp[y1l * 6 + a0];           \
        __half2 v1a = Wp[y0l * 6 + a1], v1b = Wp[y1l * 6 + a1];           \
        __half2 v2a = Wp[y0l * 6 + b1i], v2b = Wp[y1l * 6 + b1i];         \
        __half2 v0 = __hfma2(fy2, __hsub2(v0b, v0a), v0a);                \
        __half2 v1 = __hfma2(fy2, __hsub2(v1b, v1a), v1a);                \
        __half2 v2 = __hfma2(fy2, __hsub2(v2b, v2a), v2a);                \
        __half2 dA = __hsub2(v1, v0), dB = __hsub2(v2, v1);               \
        acc[0] = __hfma2(__hfma2(K0, dA, v0), RR[0 + DX], acc[0]);        \
        acc[1] = __hfma2(__hfma2(K1, dA, v0), RR[1 + DX], acc[1]);        \
        acc[2] = __hfma2(__hfma2(K2, dA, v0), RR[2 + DX], acc[2]);        \
        acc[3] = __hfma2(__hfma2(K3, dA, v0), RR[3 + DX], acc[3]);        \
        acc[4] = __hfma2(__hfma2(K4, dB, v1), RR[4 + DX], acc[4]);        \
        acc[5] = __hfma2(__hfma2(K5, dB, v1), RR[5 + DX], acc[5]);        \
        acc[6] = __hfma2(__hfma2(K6, dB, v1), RR[6 + DX], acc[6]);        \
        acc[7] = __hfma2(__hfma2(K7, dB, v1), RR[7 + DX], acc[7]);        \
    }
    TAP(ra, 0, 0) TAP(ra, 1, 1) TAP(ra, 2, 2)
    TAP(rb, 3, 0) TAP(rb, 4, 1) TAP(rb, 5, 2)
    TAP(rcr, 6, 0) TAP(rcr, 7, 1) TAP(rcr, 8, 2)
#undef TAP

    float g[8];
    float tsum = 0.f;
#pragma unroll
    for (int i = 0; i < 8; i++) {
        float2 f = __half22float2(acc[i]);
        g[i] = f.x * f.y;
        tsum += g[i];
    }
    __half2* op =
        (__half2*)(g_xsg + (b * CC + chp) * HW + h * 256 + w0 + seg);
    op[0] = __floats2half2_rn(g[0], g[1]);
    op[1] = __floats2half2_rn(g[2], g[3]);
    op[2] = __floats2half2_rn(g[4], g[5]);
    op[3] = __floats2half2_rn(g[6], g[7]);

#pragma unroll
    for (int off = 16; off; off >>= 1)
        tsum += __shfl_xor_sync(0xffffffffu, tsum, off);
    if ((tid & 31) == 0) red[tid >> 5] = tsum;
    __syncthreads();
    if (tid == 0)
        g_part[(b * CC + chp) * 64 + tile] = red[0] + red[1] + red[2] + red[3];
}

// =====================================================================
// K3: deterministic reduction of partials + SCA 1x1 conv -> g_s
// =====================================================================
__global__ void k3(const float* __restrict__ sw, const float* __restrict__ sbias) {
    __shared__ float mean_sm[128];
    int tid = threadIdx.x;  // 128 = 4 batches x 32 channels
    int b = tid >> 5, c = tid & 31;
    float sum = 0.f;
    for (int t = 0; t < 64; t++) sum += g_part[(b * CC + c) * 64 + t];
    mean_sm[tid] = sum * (1.f / 65536.f);
    __syncthreads();
    float acc = sbias[c];
#pragma unroll
    for (int k = 0; k < 32; k++) acc += sw[c * 32 + k] * mean_sm[b * 32 + k];
    g_s[tid] = acc;
}

// =====================================================================
// K4: x*s -> conv3 -> y = inp + beta*x -> LN2 -> conv4 -> gate -> conv5
//     -> out. PIXEL-PAIR (R12 exact — best known, 54.6 us).
// =====================================================================
__global__ __launch_bounds__(128) void k4(const float* __restrict__ inp,
                                          const float* __restrict__ w3,
                                          const float* __restrict__ b3g,
                                          const float* __restrict__ w4,
                                          const float* __restrict__ b4g,
                                          const float* __restrict__ w5,
                                          const float* __restrict__ b5g,
                                          const float* __restrict__ n2wg,
                                          const float* __restrict__ n2bg,
                                          const float* __restrict__ betag,
                                          const float* __restrict__ gammag,
                                          float* __restrict__ out) {
    __shared__ __align__(16) __half2 w3h[32 * 16];  // [o][c2] channel pairs
    __shared__ __align__(16) __half2 w4h[64 * 16];
    __shared__ __align__(16) __half2 w5h[32 * 16];
    __shared__ float sv[32], n2w[32], n2b[32], bet[32], gam[32];
    __shared__ float b3s[32], b4s[64], b5s[32];

    int tid = threadIdx.x;
    int p = blockIdx.x * 256 + tid * 2;  // 2 pixels per thread
    int b = p >> 16, pix = p & 65535;

    for (int i = tid; i < 512; i += 128) {
        int o = i >> 4, c2 = i & 15;
        w3h[i] = __floats2half2_rn(w3[o * 32 + 2 * c2], w3[o * 32 + 2 * c2 + 1]);
        w5h[i] = __floats2half2_rn(w5[o * 32 + 2 * c2], w5[o * 32 + 2 * c2 + 1]);
    }
    for (int i = tid; i < 1024; i += 128) {
        int o = i >> 4, c2 = i & 15;
        w4h[i] = __floats2half2_rn(w4[o * 32 + 2 * c2], w4[o * 32 + 2 * c2 + 1]);
    }
    if (tid < 32) {
        sv[tid] = g_s[b * 32 + tid];
        n2w[tid] = n2wg[tid];
        n2b[tid] = n2bg[tid];
        bet[tid] = betag[tid];
        gam[tid] = gammag[tid];
        b3s[tid] = b3g[tid];
        b5s[tid] = b5g[tid];
    }
    if (tid < 64) b4s[tid] = b4g[tid];
    __syncthreads();

    // x = gate_out * s (fp16 half2 loads: lanes = pixels); repack to
    // channel-paired half2 per pixel.
    __half2 xh0[16], xh1[16];
    {
        const __half* xg = g_xsg + b * CC * HW + pix;
#pragma unroll
        for (int c2 = 0; c2 < 16; c2++) {
            float2 fa = __half22float2(*(const __half2*)&xg[(2 * c2) * HW]);
            float2 fb = __half22float2(*(const __half2*)&xg[(2 * c2 + 1) * HW]);
            float s0 = sv[2 * c2], s1 = sv[2 * c2 + 1];
            xh0[c2] = __floats2half2_rn(fa.x * s0, fb.x * s1);  // pixel 0
            xh1[c2] = __floats2half2_rn(fa.y * s0, fb.y * s1);  // pixel 1
        }
    }

    // ---- conv3 (HFMA2, weights shared across pixels) + residual ----
    u64 yp0[16], yp1[16];  // channel pairs per pixel (fp32)
    const float* ip = inp + b * CC * HW + pix;
#pragma unroll 2
    for (int j = 0; j < 16; j++) {
        __half2 z = __floats2half2_rn(0.f, 0.f);
        __half2 a00 = z, a10 = z, a01 = z, a11 = z;
        const __half2* wr0 = &w3h[(2 * j) * 16];
        const __half2* wr1 = &w3h[(2 * j + 1) * 16];
#pragma unroll
        for (int c2 = 0; c2 < 16; c2++) {
            __half2 w0 = wr0[c2], w1 = wr1[c2];
            a00 = __hfma2(w0, xh0[c2], a00);
            a01 = __hfma2(w0, xh1[c2], a01);
            a10 = __hfma2(w1, xh0[c2], a10);
            a11 = __hfma2(w1, xh1[c2], a11);
        }
        float2 i0 = *(const float2*)&ip[(2 * j) * HW];      // (p0,p1)
        float2 i1 = *(const float2*)&ip[(2 * j + 1) * HW];
        float bt0 = bet[2 * j], bt1 = bet[2 * j + 1];
        float bb0 = b3s[2 * j], bb1 = b3s[2 * j + 1];
        yp0[j] = pack2(i0.x + bt0 * (bb0 + hsum2h(a00)),
                       i1.x + bt1 * (bb1 + hsum2h(a10)));
        yp1[j] = pack2(i0.y + bt0 * (bb0 + hsum2h(a01)),
                       i1.y + bt1 * (bb1 + hsum2h(a11)));
    }

    // ---- LN2 per pixel -> zh (reuse xh regs) ----
    {
        u64 sa0 = 0ull, qa0 = 0ull, sa1 = 0ull, qa1 = 0ull;
#pragma unroll
        for (int j = 0; j < 16; j++) {
            sa0 = add2(sa0, yp0[j]);
            qa0 = ffma2(yp0[j], yp0[j], qa0);
            sa1 = add2(sa1, yp1[j]);
            qa1 = ffma2(yp1[j], yp1[j], qa1);
        }
        float s0 = hsum2(sa0), q0 = hsum2(qa0);
        float s1 = hsum2(sa1), q1 = hsum2(qa1);
        float mu0 = s0 * (1.f / 32.f);
        float mu1 = s1 * (1.f / 32.f);
        float rstd0 = rsqrtf(q0 * (1.f / 32.f) - mu0 * mu0 + 1e-6f);
        float rstd1 = rsqrtf(q1 * (1.f / 32.f) - mu1 * mu1 + 1e-6f);
#pragma unroll
        for (int j = 0; j < 16; j++) {
            float w0 = n2w[2 * j], w1 = n2w[2 * j + 1];
            float c0 = n2b[2 * j], c1 = n2b[2 * j + 1];
            float2 f0 = unpack2(yp0[j]);
            float2 f1 = unpack2(yp1[j]);
            xh0[j] = __floats2half2_rn((f0.x - mu0) * rstd0 * w0 + c0,
                                       (f0.y - mu0) * rstd0 * w1 + c1);
            xh1[j] = __floats2half2_rn((f1.x - mu1) * rstd1 * w0 + c0,
                                       (f1.y - mu1) * rstd1 * w1 + c1);
        }
    }

    // ---- conv4 (64 outs, HFMA2, shared weights) + gate -> gh ----
    __half2 gh0[16], gh1[16];
#pragma unroll 2
    for (int j = 0; j < 16; j++) {
        __half2 z = __floats2half2_rn(0.f, 0.f);
        __half2 aA0 = z, aB0 = z, aC0 = z, aD0 = z;
        __half2 aA1 = z, aB1 = z, aC1 = z, aD1 = z;
        const __half2* wA = &w4h[(2 * j) * 16];
        const __half2* wB = &w4h[(2 * j + 1) * 16];
        const __half2* wC = &w4h[(2 * j + 32) * 16];
        const __half2* wD = &w4h[(2 * j + 33) * 16];
#pragma unroll
        for (int c2 = 0; c2 < 16; c2++) {
            __half2 x0 = xh0[c2], x1 = xh1[c2];
            __half2 wa = wA[c2], wb = wB[c2], wc = wC[c2], wd = wD[c2];
            aA0 = __hfma2(wa, x0, aA0);
            aA1 = __hfma2(wa, x1, aA1);
            aB0 = __hfma2(wb, x0, aB0);
            aB1 = __hfma2(wb, x1, aB1);
            aC0 = __hfma2(wc, x0, aC0);
            aC1 = __hfma2(wc, x1, aC1);
            aD0 = __hfma2(wd, x0, aD0);
            aD1 = __hfma2(wd, x1, aD1);
        }
        float bA = b4s[2 * j], bB = b4s[2 * j + 1];
        float bC = b4s[2 * j + 32], bD = b4s[2 * j + 33];
        gh0[j] = __floats2half2_rn((bA + hsum2h(aA0)) * (bC + hsum2h(aC0)),
                                   (bB + hsum2h(aB0)) * (bD + hsum2h(aD0)));
        gh1[j] = __floats2half2_rn((bA + hsum2h(aA1)) * (bC + hsum2h(aC1)),
                                   (bB + hsum2h(aB1)) * (bD + hsum2h(aD1)));
    }

    // ---- conv5 (HFMA2, shared weights) + final residual ----
    float* op = out + b * CC * HW + pix;
#pragma unroll 2
    for (int j = 0; j < 16; j++) {
        __half2 z = __floats2half2_rn(0.f, 0.f);
        __half2 a00 = z, a10 = z, a01 = z, a11 = z;
        const __half2* wr0 = &w5h[(2 * j) * 16];
        const __half2* wr1 = &w5h[(2 * j + 1) * 16];
#pragma unroll
        for (int c2 = 0; c2 < 16; c2++) {
            __half2 w0 = wr0[c2], w1 = wr1[c2];
            a00 = __hfma2(w0, gh0[c2], a00);
            a01 = __hfma2(w0, gh1[c2], a01);
            a10 = __hfma2(w1, gh0[c2], a10);
            a11 = __hfma2(w1, gh1[c2], a11);
        }
        float gm0 = gam[2 * j], gm1 = gam[2 * j + 1];
        float bb0 = b5s[2 * j], bb1 = b5s[2 * j + 1];
        float2 f0 = unpack2(yp0[j]);  // (ch even, ch odd) pixel 0
        float2 f1 = unpack2(yp1[j]);  // pixel 1
        *(float2*)&op[(2 * j) * HW] =
            make_float2(f0.x + gm0 * (bb0 + hsum2h(a00)),
                        f1.x + gm0 * (bb0 + hsum2h(a01)));
        *(float2*)&op[(2 * j + 1) * HW] =
            make_float2(f0.y + gm1 * (bb1 + hsum2h(a10)),
                        f1.y + gm1 * (bb1 + hsum2h(a11)));
    }
}

extern "C" void kernel_launch(void* const* d_in, const int* in_sizes, int n_in,
                              void* d_out, int out_size) {
    const float* inp     = (const float*)d_in[0];
    const float* w2      = (const float*)d_in[1];
    const float* conv1_w = (const float*)d_in[2];
    const float* conv1_b = (const float*)d_in[3];
    const float* conv3_w = (const float*)d_in[4];
    const float* conv3_b = (const float*)d_in[5];
    const float* sca_w   = (const float*)d_in[6];
    const float* sca_b   = (const float*)d_in[7];
    const float* conv4_w = (const float*)d_in[8];
    const float* conv4_b = (const float*)d_in[9];
    const float* conv5_w = (const float*)d_in[10];
    const float* conv5_b = (const float*)d_in[11];
    const float* norm1_w = (const float*)d_in[12];
    const float* norm1_b = (const float*)d_in[13];
    const float* norm2_w = (const float*)d_in[14];
    const float* norm2_b = (const float*)d_in[15];
    const float* beta    = (const float*)d_in[16];
    const float* gamma   = (const float*)d_in[17];
    float* out = (float*)d_out;

    k1<<<1024, 128>>>(inp, conv1_w, conv1_b, norm1_w, norm1_b);
    k2<<<dim3(64, 32, 4), 128>>>(w2);
    k3<<<1, 128>>>(sca_w, sca_b);
    k4<<<1024, 128>>>(inp, conv3_w, conv3_b, conv4_w, conv4_b, conv5_w, conv5_b,
                      norm2_w, norm2_b, beta, gamma, out);
}

// round 15
// speedup vs baseline: 1.2842x; 1.0333x over previous
#include <cuda_runtime.h>
#include <cuda_fp16.h>

typedef unsigned long long u64;

// Problem constants
#define BB 4
#define CC 32
#define DW 64
#define HH 256
#define WW 256
#define HW 65536

// Scratch (device globals: allocation-free rule). fp16 intermediates.
// g_tp: conv1 output in channel-pair-interleaved layout:
//   g_tp[(b*32 + o)*HW + pix] = (ch o, ch o+32) as half2.
__device__ __half2 g_tp[BB * 32 * HW];  // 32 MB
__device__ __half g_xsg[BB * CC * HW];  // gate output, 16 MB
__device__ float g_part[BB * CC * 64];  // per-(b,ch,tile) partial sums
__device__ float g_s[BB * CC];          // SCA scale per (b,ch)

// ---- packed fp32x2 helpers (sm_100+) ----
__device__ __forceinline__ u64 pack2(float lo, float hi) {
    u64 r;
    asm("mov.b64 %0, {%1,%2};" : "=l"(r) : "f"(lo), "f"(hi));
    return r;
}
__device__ __forceinline__ float2 unpack2(u64 v) {
    float lo, hi;
    asm("mov.b64 {%0,%1}, %2;" : "=f"(lo), "=f"(hi) : "l"(v));
    return make_float2(lo, hi);
}
__device__ __forceinline__ u64 ffma2(u64 a, u64 b, u64 c) {
    u64 d;
    asm("fma.rn.f32x2 %0, %1, %2, %3;" : "=l"(d) : "l"(a), "l"(b), "l"(c));
    return d;
}
__device__ __forceinline__ u64 add2(u64 a, u64 b) {
    u64 d;
    asm("add.rn.f32x2 %0, %1, %2;" : "=l"(d) : "l"(a), "l"(b));
    return d;
}
__device__ __forceinline__ u64 mul2(u64 a, u64 b) {
    u64 d;
    asm("mul.rn.f32x2 %0, %1, %2;" : "=l"(d) : "l"(a), "l"(b));
    return d;
}
__device__ __forceinline__ float hsum2(u64 v) {
    float2 f = unpack2(v);
    return f.x + f.y;
}
__device__ __forceinline__ float hsum2h(__half2 v) {
    float2 f = __half22float2(v);
    return f.x + f.y;
}
// pairwise horizontal sum: returns (hsum(a), hsum(b)) as half2
__device__ __forceinline__ __half2 psum2(__half2 a, __half2 b) {
    return __hadd2(__lows2half2(a, b), __highs2half2(a, b));
}

// =====================================================================
// K1: LayerNorm + conv1 (32 -> 64), pixel-pair, interleaved g_tp output.
// Epilogue via psum2 + half2 bias (output-pair form).
// =====================================================================
__global__ __launch_bounds__(128) void k1(const float* __restrict__ inp,
                                          const float* __restrict__ w1,
                                          const float* __restrict__ b1g,
                                          const float* __restrict__ n1w,
                                          const float* __restrict__ n1b) {
    __shared__ __align__(16) __half2 w1h[64 * 16];  // [o][c2] channel pairs
    __shared__ __half2 sbp[32];                     // (b1[o], b1[o+32])
    __shared__ float snw[32], snb[32];
    int tid = threadIdx.x;
    for (int i = tid; i < 1024; i += 128) {
        int o = i >> 4, c2 = i & 15;
        w1h[i] = __floats2half2_rn(w1[o * 32 + 2 * c2], w1[o * 32 + 2 * c2 + 1]);
    }
    if (tid < 32) {
        snw[tid] = n1w[tid];
        snb[tid] = n1b[tid];
        sbp[tid] = __floats2half2_rn(b1g[tid], b1g[tid + 32]);
    }
    __syncthreads();

    int p = blockIdx.x * 256 + tid * 2;  // 2 pixels per thread
    int b = p >> 16, pix = p & 65535;
    const float* ip = inp + b * CC * HW + pix;

    u64 xv[32];
    u64 sa = 0ull, qa = 0ull;
#pragma unroll
    for (int c = 0; c < 32; c++) {
        float2 v = *(const float2*)&ip[c * HW];
        u64 t = pack2(v.x, v.y);
        xv[c] = t;
        sa = add2(sa, t);
        qa = ffma2(t, t, qa);
    }
    u64 nmu = mul2(sa, pack2(-1.f / 32.f, -1.f / 32.f));
    float2 qf = unpack2(qa);
    float2 nm = unpack2(nmu);
    float var0 = qf.x * (1.f / 32.f) - nm.x * nm.x;
    float var1 = qf.y * (1.f / 32.f) - nm.y * nm.y;
    u64 rs2 = pack2(rsqrtf(var0 + 1e-6f), rsqrtf(var1 + 1e-6f));

    __half2 xh0[16], xh1[16];
#pragma unroll
    for (int c2 = 0; c2 < 16; c2++) {
        int ca = 2 * c2, cb = 2 * c2 + 1;
        u64 ta = mul2(add2(xv[ca], nmu), rs2);
        u64 tb = mul2(add2(xv[cb], nmu), rs2);
        u64 za = ffma2(ta, pack2(snw[ca], snw[ca]), pack2(snb[ca], snb[ca]));
        u64 zb = ffma2(tb, pack2(snw[cb], snw[cb]), pack2(snb[cb], snb[cb]));
        float2 fa = unpack2(za), fb = unpack2(zb);
        xh0[c2] = __floats2half2_rn(fa.x, fb.x);
        xh1[c2] = __floats2half2_rn(fa.y, fb.y);
    }

    __half2* op = g_tp + b * 32 * HW + pix;
#pragma unroll 2
    for (int o = 0; o < 32; o++) {
        __half2 z = __floats2half2_rn(0.f, 0.f);
        __half2 aL0 = z, aL1 = z, aH0 = z, aH1 = z;
        const __half2* wrL = &w1h[o * 16];
        const __half2* wrH = &w1h[(o + 32) * 16];
#pragma unroll
        for (int c2 = 0; c2 < 16; c2++) {
            __half2 x0 = xh0[c2], x1 = xh1[c2];
            aL0 = __hfma2(wrL[c2], x0, aL0);
            aL1 = __hfma2(wrL[c2], x1, aL1);
            aH0 = __hfma2(wrH[c2], x0, aH0);
            aH1 = __hfma2(wrH[c2], x1, aH1);
        }
        __half2 bp = sbp[o];
        __half2 p0 = __hadd2(bp, psum2(aL0, aH0));
        __half2 p1 = __hadd2(bp, psum2(aL1, aH1));
        __half2* dst = op + o * HW;  // pix even -> 8B-aligned pair
        dst[0] = p0;
        dst[1] = p1;
    }
}

// =====================================================================
// K2: DDF + SimpleGate + SCA partials — HALF2-LANE (frozen from R14).
// =====================================================================
__global__ __launch_bounds__(128) void k2(const float* __restrict__ w2g) {
    int tile = blockIdx.x;  // 0..63
    int chp = blockIdx.y;   // 0..31
    int b = blockIdx.z;
    int tyi = tile >> 3, txi = tile & 7;
    int h0 = tyi * 32, w0 = txi * 32;
    const int TSTR = 35;  // smem row stride in half2 elems

    __shared__ __align__(16) __half2 tin[34 * TSTR];  // (ch0, ch1) per px
    __shared__ __align__(16) __half2 Wc[9][36];       // (ch0, ch1) per wgt
    __shared__ float red[4];

    int tid = threadIdx.x;

    {
        const __half2* src = g_tp + (b * 32 + chp) * HW;
        __half2 hz = __floats2half2_rn(0.f, 0.f);
        for (int idx = tid; idx < 34 * 34; idx += 128) {
            int r = idx / 34, c = idx - r * 34;
            int gh = h0 - 1 + r, gw = w0 - 1 + c;
            __half2 v = hz;
            if ((unsigned)gh < 256u && (unsigned)gw < 256u)
                v = src[gh * 256 + gw];
            tin[r * TSTR + c] = v;
        }
    }
    {
        int ybase = 4 * tyi - 1, xbase = 4 * txi - 1;
        for (int idx = tid; idx < 324; idx += 128) {
            int t = idx / 36;
            int rc = idx - t * 36;
            int rr = rc / 6, cj = rc - rr * 6;
            int ys = min(max(ybase + rr, 0), 31);
            int xs = min(max(xbase + cj, 0), 31);
            float wv0 = w2g[(((b * 64 + chp) * 9 + t) * 32 + ys) * 32 + xs];
            float wv1 = w2g[(((b * 64 + chp + 32) * 9 + t) * 32 + ys) * 32 + xs];
            Wc[t][rc] = __floats2half2_rn(wv0, wv1);
        }
    }
    __syncthreads();

    int row = tid >> 2;        // 0..31
    int seg = (tid & 3) * 8;   // 0,8,16,24
    int h = h0 + row;

    float srcy = (h - 3.5f) * 0.125f;
    float y0f = floorf(srcy);
    float fy = srcy - y0f;
    int y0 = (int)y0f;
    int ybase = 4 * tyi - 1;
    int y0l = max(y0, 0) - ybase;
    int y1l = min(y0 + 1, 31) - ybase;

    int m = 4 * txi + (seg >> 3);
    int xbase = 4 * txi - 1;
    int a0 = max(m - 1, 0) - xbase;
    int a1 = m - xbase;
    int b1i = min(m + 1, 31) - xbase;

    __half2 fy2 = __float2half2_rn(fy);
    const __half2 K0 = __float2half2_rn(0.5625f);
    const __half2 K1 = __float2half2_rn(0.6875f);
    const __half2 K2 = __float2half2_rn(0.8125f);
    const __half2 K3 = __float2half2_rn(0.9375f);
    const __half2 K4 = __float2half2_rn(0.0625f);
    const __half2 K5 = __float2half2_rn(0.1875f);
    const __half2 K6 = __float2half2_rn(0.3125f);
    const __half2 K7 = __float2half2_rn(0.4375f);

    __half2 ra[10], rb[10], rcr[10];
#pragma unroll
    for (int k = 0; k < 10; k++) {
        ra[k] = tin[row * TSTR + seg + k];
        rb[k] = tin[(row + 1) * TSTR + seg + k];
        rcr[k] = tin[(row + 2) * TSTR + seg + k];
    }

    __half2 acc[8];
#pragma unroll
    for (int i = 0; i < 8; i++) acc[i] = __floats2half2_rn(0.f, 0.f);

#define TAP(RR, T, DX)                                                    \
    {                                                                     \
        const __half2* Wp = Wc[T];                                        \
        __half2 v0a = Wp[y0l * 6 + a0], v0b = Wp[y1l * 6 + a0];           \
        __half2 v1a = Wp[y0l * 6 + a1], v1b = Wp[y1l * 6 + a1];           \
        __half2 v2a = Wp[y0l * 6 + b1i], v2b = Wp[y1l * 6 + b1i];         \
        __half2 v0 = __hfma2(fy2, __hsub2(v0b, v0a), v0a);                \
        __half2 v1 = __hfma2(fy2, __hsub2(v1b, v1a), v1a);                \
        __half2 v2 = __hfma2(fy2, __hsub2(v2b, v2a), v2a);                \
        __half2 dA = __hsub2(v1, v0), dB = __hsub2(v2, v1);               \
        acc[0] = __hfma2(__hfma2(K0, dA, v0), RR[0 + DX], acc[0]);        \
        acc[1] = __hfma2(__hfma2(K1, dA, v0), RR[1 + DX], acc[1]);        \
        acc[2] = __hfma2(__hfma2(K2, dA, v0), RR[2 + DX], acc[2]);        \
        acc[3] = __hfma2(__hfma2(K3, dA, v0), RR[3 + DX], acc[3]);        \
        acc[4] = __hfma2(__hfma2(K4, dB, v1), RR[4 + DX], acc[4]);        \
        acc[5] = __hfma2(__hfma2(K5, dB, v1), RR[5 + DX], acc[5]);        \
        acc[6] = __hfma2(__hfma2(K6, dB, v1), RR[6 + DX], acc[6]);        \
        acc[7] = __hfma2(__hfma2(K7, dB, v1), RR[7 + DX], acc[7]);        \
    }
    TAP(ra, 0, 0) TAP(ra, 1, 1) TAP(ra, 2, 2)
    TAP(rb, 3, 0) TAP(rb, 4, 1) TAP(rb, 5, 2)
    TAP(rcr, 6, 0) TAP(rcr, 7, 1) TAP(rcr, 8, 2)
#undef TAP

    float g[8];
    float tsum = 0.f;
#pragma unroll
    for (int i = 0; i < 8; i++) {
        float2 f = __half22float2(acc[i]);
        g[i] = f.x * f.y;
        tsum += g[i];
    }
    __half2* op =
        (__half2*)(g_xsg + (b * CC + chp) * HW + h * 256 + w0 + seg);
    op[0] = __floats2half2_rn(g[0], g[1]);
    op[1] = __floats2half2_rn(g[2], g[3]);
    op[2] = __floats2half2_rn(g[4], g[5]);
    op[3] = __floats2half2_rn(g[6], g[7]);

#pragma unroll
    for (int off = 16; off; off >>= 1)
        tsum += __shfl_xor_sync(0xffffffffu, tsum, off);
    if ((tid & 31) == 0) red[tid >> 5] = tsum;
    __syncthreads();
    if (tid == 0)
        g_part[(b * CC + chp) * 64 + tile] = red[0] + red[1] + red[2] + red[3];
}

// =====================================================================
// K3: deterministic reduction of partials + SCA 1x1 conv -> g_s
// =====================================================================
__global__ void k3(const float* __restrict__ sw, const float* __restrict__ sbias) {
    __shared__ float mean_sm[128];
    int tid = threadIdx.x;  // 128 = 4 batches x 32 channels
    int b = tid >> 5, c = tid & 31;
    float sum = 0.f;
    for (int t = 0; t < 64; t++) sum += g_part[(b * CC + c) * 64 + t];
    mean_sm[tid] = sum * (1.f / 65536.f);
    __syncthreads();
    float acc = sbias[c];
#pragma unroll
    for (int k = 0; k < 32; k++) acc += sw[c * 32 + k] * mean_sm[b * 32 + k];
    g_s[tid] = acc;
}

// =====================================================================
// K4: x*s -> conv3 -> y = inp + beta*x -> LN2 -> conv4 -> gate -> conv5
//     -> out. PIXEL-PAIR with psum2 epilogues (conv4 fully in half2).
// =====================================================================
__global__ __launch_bounds__(128) void k4(const float* __restrict__ inp,
                                          const float* __restrict__ w3,
                                          const float* __restrict__ b3g,
                                          const float* __restrict__ w4,
                                          const float* __restrict__ b4g,
                                          const float* __restrict__ w5,
                                          const float* __restrict__ b5g,
                                          const float* __restrict__ n2wg,
                                          const float* __restrict__ n2bg,
                                          const float* __restrict__ betag,
                                          const float* __restrict__ gammag,
                                          float* __restrict__ out) {
    __shared__ __align__(16) __half2 w3h[32 * 16];  // [o][c2] channel pairs
    __shared__ __align__(16) __half2 w4h[64 * 16];
    __shared__ __align__(16) __half2 w5h[32 * 16];
    __shared__ __half2 b4ab[16], b4cd[16];  // (b4[2j],b4[2j+1]) / (+32,+33)
    __shared__ float sv[32], n2w[32], n2b[32], bet[32], gam[32];
    __shared__ float b3s[32], b5s[32];

    int tid = threadIdx.x;
    int p = blockIdx.x * 256 + tid * 2;  // 2 pixels per thread
    int b = p >> 16, pix = p & 65535;

    for (int i = tid; i < 512; i += 128) {
        int o = i >> 4, c2 = i & 15;
        w3h[i] = __floats2half2_rn(w3[o * 32 + 2 * c2], w3[o * 32 + 2 * c2 + 1]);
        w5h[i] = __floats2half2_rn(w5[o * 32 + 2 * c2], w5[o * 32 + 2 * c2 + 1]);
    }
    for (int i = tid; i < 1024; i += 128) {
        int o = i >> 4, c2 = i & 15;
        w4h[i] = __floats2half2_rn(w4[o * 32 + 2 * c2], w4[o * 32 + 2 * c2 + 1]);
    }
    if (tid < 32) {
        sv[tid] = g_s[b * 32 + tid];
        n2w[tid] = n2wg[tid];
        n2b[tid] = n2bg[tid];
        bet[tid] = betag[tid];
        gam[tid] = gammag[tid];
        b3s[tid] = b3g[tid];
        b5s[tid] = b5g[tid];
    }
    if (tid < 16) {
        b4ab[tid] = __floats2half2_rn(b4g[2 * tid], b4g[2 * tid + 1]);
        b4cd[tid] = __floats2half2_rn(b4g[2 * tid + 32], b4g[2 * tid + 33]);
    }
    __syncthreads();

    // x = gate_out * s (fp16 half2 loads: lanes = pixels); repack to
    // channel-paired half2 per pixel.
    __half2 xh0[16], xh1[16];
    {
        const __half* xg = g_xsg + b * CC * HW + pix;
#pragma unroll
        for (int c2 = 0; c2 < 16; c2++) {
            float2 fa = __half22float2(*(const __half2*)&xg[(2 * c2) * HW]);
            float2 fb = __half22float2(*(const __half2*)&xg[(2 * c2 + 1) * HW]);
            float s0 = sv[2 * c2], s1 = sv[2 * c2 + 1];
            xh0[c2] = __floats2half2_rn(fa.x * s0, fb.x * s1);  // pixel 0
            xh1[c2] = __floats2half2_rn(fa.y * s0, fb.y * s1);  // pixel 1
        }
    }

    // ---- conv3 (HFMA2, weights shared across pixels) + residual ----
    u64 yp0[16], yp1[16];  // channel pairs per pixel (fp32)
    const float* ip = inp + b * CC * HW + pix;
#pragma unroll 2
    for (int j = 0; j < 16; j++) {
        __half2 z = __floats2half2_rn(0.f, 0.f);
        __half2 a00 = z, a10 = z, a01 = z, a11 = z;
        const __half2* wr0 = &w3h[(2 * j) * 16];
        const __half2* wr1 = &w3h[(2 * j + 1) * 16];
#pragma unroll
        for (int c2 = 0; c2 < 16; c2++) {
            __half2 w0 = wr0[c2], w1 = wr1[c2];
            a00 = __hfma2(w0, xh0[c2], a00);
            a01 = __hfma2(w0, xh1[c2], a01);
            a10 = __hfma2(w1, xh0[c2], a10);
            a11 = __hfma2(w1, xh1[c2], a11);
        }
        float2 f0s = __half22float2(psum2(a00, a10));  // (sum ch2j, ch2j+1) p0
        float2 f1s = __half22float2(psum2(a01, a11));  // pixel 1
        float2 i0 = *(const float2*)&ip[(2 * j) * HW];  // (p0,p1)
        float2 i1 = *(const float2*)&ip[(2 * j + 1) * HW];
        float bt0 = bet[2 * j], bt1 = bet[2 * j + 1];
        float bb0 = b3s[2 * j], bb1 = b3s[2 * j + 1];
        yp0[j] = pack2(i0.x + bt0 * (bb0 + f0s.x), i1.x + bt1 * (bb1 + f0s.y));
        yp1[j] = pack2(i0.y + bt0 * (bb0 + f1s.x), i1.y + bt1 * (bb1 + f1s.y));
    }

    // ---- LN2 per pixel -> zh (reuse xh regs) ----
    {
        u64 sa0 = 0ull, qa0 = 0ull, sa1 = 0ull, qa1 = 0ull;
#pragma unroll
        for (int j = 0; j < 16; j++) {
            sa0 = add2(sa0, yp0[j]);
            qa0 = ffma2(yp0[j], yp0[j], qa0);
            sa1 = add2(sa1, yp1[j]);
            qa1 = ffma2(yp1[j], yp1[j], qa1);
        }
        float s0 = hsum2(sa0), q0 = hsum2(qa0);
        float s1 = hsum2(sa1), q1 = hsum2(qa1);
        float mu0 = s0 * (1.f / 32.f);
        float mu1 = s1 * (1.f / 32.f);
        float rstd0 = rsqrtf(q0 * (1.f / 32.f) - mu0 * mu0 + 1e-6f);
        float rstd1 = rsqrtf(q1 * (1.f / 32.f) - mu1 * mu1 + 1e-6f);
#pragma unroll
        for (int j = 0; j < 16; j++) {
            float w0 = n2w[2 * j], w1 = n2w[2 * j + 1];
            float c0 = n2b[2 * j], c1 = n2b[2 * j + 1];
            float2 f0 = unpack2(yp0[j]);
            float2 f1 = unpack2(yp1[j]);
            xh0[j] = __floats2half2_rn((f0.x - mu0) * rstd0 * w0 + c0,
                                       (f0.y - mu0) * rstd0 * w1 + c1);
            xh1[j] = __floats2half2_rn((f1.x - mu1) * rstd1 * w0 + c0,
                                       (f1.y - mu1) * rstd1 * w1 + c1);
        }
    }

    // ---- conv4 (64 outs, HFMA2, shared weights) + gate fully in half2 ----
    __half2 gh0[16], gh1[16];
#pragma unroll 2
    for (int j = 0; j < 16; j++) {
        __half2 z = __floats2half2_rn(0.f, 0.f);
        __half2 aA0 = z, aB0 = z, aC0 = z, aD0 = z;
        __half2 aA1 = z, aB1 = z, aC1 = z, aD1 = z;
        const __half2* wA = &w4h[(2 * j) * 16];
        const __half2* wB = &w4h[(2 * j + 1) * 16];
        const __half2* wC = &w4h[(2 * j + 32) * 16];
        const __half2* wD = &w4h[(2 * j + 33) * 16];
#pragma unroll
        for (int c2 = 0; c2 < 16; c2++) {
            __half2 x0 = xh0[c2], x1 = xh1[c2];
            __half2 wa = wA[c2], wb = wB[c2], wc = wC[c2], wd = wD[c2];
            aA0 = __hfma2(wa, x0, aA0);
            aA1 = __hfma2(wa, x1, aA1);
            aB0 = __hfma2(wb, x0, aB0);
            aB1 = __hfma2(wb, x1, aB1);
            aC0 = __hfma2(wc, x0, aC0);
            aC1 = __hfma2(wc, x1, aC1);
            aD0 = __hfma2(wd, x0, aD0);
            aD1 = __hfma2(wd, x1, aD1);
        }
        __half2 bab = b4ab[j], bcd = b4cd[j];
        gh0[j] = __hmul2(__hadd2(bab, psum2(aA0, aB0)),
                         __hadd2(bcd, psum2(aC0, aD0)));
        gh1[j] = __hmul2(__hadd2(bab, psum2(aA1, aB1)),
                         __hadd2(bcd, psum2(aC1, aD1)));
    }

    // ---- conv5 (HFMA2, shared weights) + final residual ----
    float* op = out + b * CC * HW + pix;
#pragma unroll 2
    for (int j = 0; j < 16; j++) {
        __half2 z = __floats2half2_rn(0.f, 0.f);
        __half2 a00 = z, a10 = z, a01 = z, a11 = z;
        const __half2* wr0 = &w5h[(2 * j) * 16];
        const __half2* wr1 = &w5h[(2 * j + 1) * 16];
#pragma unroll
        for (int c2 = 0; c2 < 16; c2++) {
            __half2 w0 = wr0[c2], w1 = wr1[c2];
            a00 = __hfma2(w0, gh0[c2], a00);
            a01 = __hfma2(w0, gh1[c2], a01);
            a10 = __hfma2(w1, gh0[c2], a10);
            a11 = __hfma2(w1, gh1[c2], a11);
        }
        float2 f0s = __half22float2(psum2(a00, a10));  // pixel 0 sums
        float2 f1s = __half22float2(psum2(a01, a11));  // pixel 1 sums
        float gm0 = gam[2 * j], gm1 = gam[2 * j + 1];
        float bb0 = b5s[2 * j], bb1 = b5s[2 * j + 1];
        float2 f0 = unpack2(yp0[j]);  // (ch even, ch odd) pixel 0
        float2 f1 = unpack2(yp1[j]);  // pixel 1
        *(float2*)&op[(2 * j) * HW] =
            make_float2(f0.x + gm0 * (bb0 + f0s.x), f1.x + gm0 * (bb0 + f1s.x));
        *(float2*)&op[(2 * j + 1) * HW] =
            make_float2(f0.y + gm1 * (bb1 + f0s.y), f1.y + gm1 * (bb1 + f1s.y));
    }
}

extern "C" void kernel_launch(void* const* d_in, const int* in_sizes, int n_in,
                              void* d_out, int out_size) {
    const float* inp     = (const float*)d_in[0];
    const float* w2      = (const float*)d_in[1];
    const float* conv1_w = (const float*)d_in[2];
    const float* conv1_b = (const float*)d_in[3];
    const float* conv3_w = (const float*)d_in[4];
    const float* conv3_b = (const float*)d_in[5];
    const float* sca_w   = (const float*)d_in[6];
    const float* sca_b   = (const float*)d_in[7];
    const float* conv4_w = (const float*)d_in[8];
    const float* conv4_b = (const float*)d_in[9];
    const float* conv5_w = (const float*)d_in[10];
    const float* conv5_b = (const float*)d_in[11];
    const float* norm1_w = (const float*)d_in[12];
    const float* norm1_b = (const float*)d_in[13];
    const float* norm2_w = (const float*)d_in[14];
    const float* norm2_b = (const float*)d_in[15];
    const float* beta    = (const float*)d_in[16];
    const float* gamma   = (const float*)d_in[17];
    float* out = (float*)d_out;

    k1<<<1024, 128>>>(inp, conv1_w, conv1_b, norm1_w, norm1_b);
    k2<<<dim3(64, 32, 4), 128>>>(w2);
    k3<<<1, 128>>>(sca_w, sca_b);
    k4<<<1024, 128>>>(inp, conv3_w, conv3_b, conv4_w, conv4_b, conv5_w, conv5_b,
                      norm2_w, norm2_b, beta, gamma, out);
}

// round 16
// speedup vs baseline: 1.2870x; 1.0022x over previous
#include <cuda_runtime.h>
#include <cuda_fp16.h>

typedef unsigned long long u64;

// Problem constants
#define BB 4
#define CC 32
#define DW 64
#define HH 256
#define WW 256
#define HW 65536

// Scratch (device globals: allocation-free rule). fp16 intermediates.
// g_tp: conv1 output in channel-pair-interleaved layout:
//   g_tp[(b*32 + o)*HW + pix] = (ch o, ch o+32) as half2.
__device__ __half2 g_tp[BB * 32 * HW];  // 32 MB
__device__ __half g_xsg[BB * CC * HW];  // gate output, 16 MB
__device__ float g_part[BB * CC * 64];  // per-(b,ch,tile) partial sums
__device__ float g_s[BB * CC];          // SCA scale per (b,ch)
__device__ unsigned int g_ctr;          // k2 completion counter

// ---- packed fp32x2 helpers (sm_100+) ----
__device__ __forceinline__ u64 pack2(float lo, float hi) {
    u64 r;
    asm("mov.b64 %0, {%1,%2};" : "=l"(r) : "f"(lo), "f"(hi));
    return r;
}
__device__ __forceinline__ float2 unpack2(u64 v) {
    float lo, hi;
    asm("mov.b64 {%0,%1}, %2;" : "=f"(lo), "=f"(hi) : "l"(v));
    return make_float2(lo, hi);
}
__device__ __forceinline__ u64 ffma2(u64 a, u64 b, u64 c) {
    u64 d;
    asm("fma.rn.f32x2 %0, %1, %2, %3;" : "=l"(d) : "l"(a), "l"(b), "l"(c));
    return d;
}
__device__ __forceinline__ u64 add2(u64 a, u64 b) {
    u64 d;
    asm("add.rn.f32x2 %0, %1, %2;" : "=l"(d) : "l"(a), "l"(b));
    return d;
}
__device__ __forceinline__ u64 mul2(u64 a, u64 b) {
    u64 d;
    asm("mul.rn.f32x2 %0, %1, %2;" : "=l"(d) : "l"(a), "l"(b));
    return d;
}
__device__ __forceinline__ float hsum2(u64 v) {
    float2 f = unpack2(v);
    return f.x + f.y;
}
__device__ __forceinline__ float hsum2h(__half2 v) {
    float2 f = __half22float2(v);
    return f.x + f.y;
}
// pairwise horizontal sum: returns (hsum(a), hsum(b)) as half2
__device__ __forceinline__ __half2 psum2(__half2 a, __half2 b) {
    return __hadd2(__lows2half2(a, b), __highs2half2(a, b));
}

// =====================================================================
// K1: LayerNorm + conv1 (32 -> 64), pixel-pair, interleaved g_tp output.
// Also resets the k2 completion counter (block 0, thread 0).
// =====================================================================
__global__ __launch_bounds__(128) void k1(const float* __restrict__ inp,
                                          const float* __restrict__ w1,
                                          const float* __restrict__ b1g,
                                          const float* __restrict__ n1w,
                                          const float* __restrict__ n1b) {
    __shared__ __align__(16) __half2 w1h[64 * 16];  // [o][c2] channel pairs
    __shared__ __half2 sbp[32];                     // (b1[o], b1[o+32])
    __shared__ float snw[32], snb[32];
    int tid = threadIdx.x;
    if (blockIdx.x == 0 && tid == 0) g_ctr = 0u;
    for (int i = tid; i < 1024; i += 128) {
        int o = i >> 4, c2 = i & 15;
        w1h[i] = __floats2half2_rn(w1[o * 32 + 2 * c2], w1[o * 32 + 2 * c2 + 1]);
    }
    if (tid < 32) {
        snw[tid] = n1w[tid];
        snb[tid] = n1b[tid];
        sbp[tid] = __floats2half2_rn(b1g[tid], b1g[tid + 32]);
    }
    __syncthreads();

    int p = blockIdx.x * 256 + tid * 2;  // 2 pixels per thread
    int b = p >> 16, pix = p & 65535;
    const float* ip = inp + b * CC * HW + pix;

    u64 xv[32];
    u64 sa = 0ull, qa = 0ull;
#pragma unroll
    for (int c = 0; c < 32; c++) {
        float2 v = *(const float2*)&ip[c * HW];
        u64 t = pack2(v.x, v.y);
        xv[c] = t;
        sa = add2(sa, t);
        qa = ffma2(t, t, qa);
    }
    u64 nmu = mul2(sa, pack2(-1.f / 32.f, -1.f / 32.f));
    float2 qf = unpack2(qa);
    float2 nm = unpack2(nmu);
    float var0 = qf.x * (1.f / 32.f) - nm.x * nm.x;
    float var1 = qf.y * (1.f / 32.f) - nm.y * nm.y;
    u64 rs2 = pack2(rsqrtf(var0 + 1e-6f), rsqrtf(var1 + 1e-6f));

    __half2 xh0[16], xh1[16];
#pragma unroll
    for (int c2 = 0; c2 < 16; c2++) {
        int ca = 2 * c2, cb = 2 * c2 + 1;
        u64 ta = mul2(add2(xv[ca], nmu), rs2);
        u64 tb = mul2(add2(xv[cb], nmu), rs2);
        u64 za = ffma2(ta, pack2(snw[ca], snw[ca]), pack2(snb[ca], snb[ca]));
        u64 zb = ffma2(tb, pack2(snw[cb], snw[cb]), pack2(snb[cb], snb[cb]));
        float2 fa = unpack2(za), fb = unpack2(zb);
        xh0[c2] = __floats2half2_rn(fa.x, fb.x);
        xh1[c2] = __floats2half2_rn(fa.y, fb.y);
    }

    __half2* op = g_tp + b * 32 * HW + pix;
#pragma unroll 2
    for (int o = 0; o < 32; o++) {
        __half2 z = __floats2half2_rn(0.f, 0.f);
        __half2 aL0 = z, aL1 = z, aH0 = z, aH1 = z;
        const __half2* wrL = &w1h[o * 16];
        const __half2* wrH = &w1h[(o + 32) * 16];
#pragma unroll
        for (int c2 = 0; c2 < 16; c2++) {
            __half2 x0 = xh0[c2], x1 = xh1[c2];
            aL0 = __hfma2(wrL[c2], x0, aL0);
            aL1 = __hfma2(wrL[c2], x1, aL1);
            aH0 = __hfma2(wrH[c2], x0, aH0);
            aH1 = __hfma2(wrH[c2], x1, aH1);
        }
        __half2 bp = sbp[o];
        __half2 p0 = __hadd2(bp, psum2(aL0, aH0));
        __half2 p1 = __hadd2(bp, psum2(aL1, aH1));
        __half2* dst = op + o * HW;  // pix even -> 8B-aligned pair
        dst[0] = p0;
        dst[1] = p1;
    }
}

// =====================================================================
// K2: DDF + SimpleGate + SCA partials — HALF2-LANE. The LAST block to
// finish also performs K3 (partial reduction + SCA 1x1 conv -> g_s);
// deterministic because the work is independent of which block is last.
// =====================================================================
__global__ __launch_bounds__(128) void k2(const float* __restrict__ w2g,
                                          const float* __restrict__ sw,
                                          const float* __restrict__ sbias) {
    int tile = blockIdx.x;  // 0..63
    int chp = blockIdx.y;   // 0..31
    int b = blockIdx.z;
    int tyi = tile >> 3, txi = tile & 7;
    int h0 = tyi * 32, w0 = txi * 32;
    const int TSTR = 35;  // smem row stride in half2 elems

    __shared__ __align__(16) __half2 tin[34 * TSTR];  // (ch0, ch1) per px
    __shared__ __align__(16) __half2 Wc[9][36];       // (ch0, ch1) per wgt
    __shared__ float red[4];
    __shared__ int is_last;

    int tid = threadIdx.x;

    {
        const __half2* src = g_tp + (b * 32 + chp) * HW;
        __half2 hz = __floats2half2_rn(0.f, 0.f);
        for (int idx = tid; idx < 34 * 34; idx += 128) {
            int r = idx / 34, c = idx - r * 34;
            int gh = h0 - 1 + r, gw = w0 - 1 + c;
            __half2 v = hz;
            if ((unsigned)gh < 256u && (unsigned)gw < 256u)
                v = src[gh * 256 + gw];
            tin[r * TSTR + c] = v;
        }
    }
    {
        int ybase = 4 * tyi - 1, xbase = 4 * txi - 1;
        for (int idx = tid; idx < 324; idx += 128) {
            int t = idx / 36;
            int rc = idx - t * 36;
            int rr = rc / 6, cj = rc - rr * 6;
            int ys = min(max(ybase + rr, 0), 31);
            int xs = min(max(xbase + cj, 0), 31);
            float wv0 = w2g[(((b * 64 + chp) * 9 + t) * 32 + ys) * 32 + xs];
            float wv1 = w2g[(((b * 64 + chp + 32) * 9 + t) * 32 + ys) * 32 + xs];
            Wc[t][rc] = __floats2half2_rn(wv0, wv1);
        }
    }
    __syncthreads();

    int row = tid >> 2;        // 0..31
    int seg = (tid & 3) * 8;   // 0,8,16,24
    int h = h0 + row;

    float srcy = (h - 3.5f) * 0.125f;
    float y0f = floorf(srcy);
    float fy = srcy - y0f;
    int y0 = (int)y0f;
    int ybase = 4 * tyi - 1;
    int y0l = max(y0, 0) - ybase;
    int y1l = min(y0 + 1, 31) - ybase;

    int m = 4 * txi + (seg >> 3);
    int xbase = 4 * txi - 1;
    int a0 = max(m - 1, 0) - xbase;
    int a1 = m - xbase;
    int b1i = min(m + 1, 31) - xbase;

    __half2 fy2 = __float2half2_rn(fy);
    const __half2 K0 = __float2half2_rn(0.5625f);
    const __half2 K1 = __float2half2_rn(0.6875f);
    const __half2 K2 = __float2half2_rn(0.8125f);
    const __half2 K3 = __float2half2_rn(0.9375f);
    const __half2 K4 = __float2half2_rn(0.0625f);
    const __half2 K5 = __float2half2_rn(0.1875f);
    const __half2 K6 = __float2half2_rn(0.3125f);
    const __half2 K7 = __float2half2_rn(0.4375f);

    __half2 ra[10], rb[10], rcr[10];
#pragma unroll
    for (int k = 0; k < 10; k++) {
        ra[k] = tin[row * TSTR + seg + k];
        rb[k] = tin[(row + 1) * TSTR + seg + k];
        rcr[k] = tin[(row + 2) * TSTR + seg + k];
    }

    __half2 acc[8];
#pragma unroll
    for (int i = 0; i < 8; i++) acc[i] = __floats2half2_rn(0.f, 0.f);

#define TAP(RR, T, DX)                                                    \
    {                                                                     \
        const __half2* Wp = Wc[T];                                        \
        __half2 v0a = Wp[y0l * 6 + a0], v0b = Wp[y1l * 6 + a0];           \
        __half2 v1a = Wp[y0l * 6 + a1], v1b = Wp[y1l * 6 + a1];           \
        __half2 v2a = Wp[y0l * 6 + b1i], v2b = Wp[y1l * 6 + b1i];         \
        __half2 v0 = __hfma2(fy2, __hsub2(v0b, v0a), v0a);                \
        __half2 v1 = __hfma2(fy2, __hsub2(v1b, v1a), v1a);                \
        __half2 v2 = __hfma2(fy2, __hsub2(v2b, v2a), v2a);                \
        __half2 dA = __hsub2(v1, v0), dB = __hsub2(v2, v1);               \
        acc[0] = __hfma2(__hfma2(K0, dA, v0), RR[0 + DX], acc[0]);        \
        acc[1] = __hfma2(__hfma2(K1, dA, v0), RR[1 + DX], acc[1]);        \
        acc[2] = __hfma2(__hfma2(K2, dA, v0), RR[2 + DX], acc[2]);        \
        acc[3] = __hfma2(__hfma2(K3, dA, v0), RR[3 + DX], acc[3]);        \
        acc[4] = __hfma2(__hfma2(K4, dB, v1), RR[4 + DX], acc[4]);        \
        acc[5] = __hfma2(__hfma2(K5, dB, v1), RR[5 + DX], acc[5]);        \
        acc[6] = __hfma2(__hfma2(K6, dB, v1), RR[6 + DX], acc[6]);        \
        acc[7] = __hfma2(__hfma2(K7, dB, v1), RR[7 + DX], acc[7]);        \
    }
    TAP(ra, 0, 0) TAP(ra, 1, 1) TAP(ra, 2, 2)
    TAP(rb, 3, 0) TAP(rb, 4, 1) TAP(rb, 5, 2)
    TAP(rcr, 6, 0) TAP(rcr, 7, 1) TAP(rcr, 8, 2)
#undef TAP

    float g[8];
    float tsum = 0.f;
#pragma unroll
    for (int i = 0; i < 8; i++) {
        float2 f = __half22float2(acc[i]);
        g[i] = f.x * f.y;
        tsum += g[i];
    }
    __half2* op =
        (__half2*)(g_xsg + (b * CC + chp) * HW + h * 256 + w0 + seg);
    op[0] = __floats2half2_rn(g[0], g[1]);
    op[1] = __floats2half2_rn(g[2], g[3]);
    op[2] = __floats2half2_rn(g[4], g[5]);
    op[3] = __floats2half2_rn(g[6], g[7]);

#pragma unroll
    for (int off = 16; off; off >>= 1)
        tsum += __shfl_xor_sync(0xffffffffu, tsum, off);
    if ((tid & 31) == 0) red[tid >> 5] = tsum;
    __syncthreads();
    if (tid == 0) {
        g_part[(b * CC + chp) * 64 + tile] = red[0] + red[1] + red[2] + red[3];
        __threadfence();
        unsigned int done = atomicAdd(&g_ctr, 1u);
        is_last = (done == 64u * 32u * 4u - 1u) ? 1 : 0;
    }
    __syncthreads();

    // Last block performs K3: deterministic reduction + SCA conv -> g_s
    if (is_last) {
        __shared__ float mean_sm[128];
        int bb = tid >> 5, c = tid & 31;
        float sum = 0.f;
        for (int t = 0; t < 64; t++) sum += g_part[(bb * CC + c) * 64 + t];
        mean_sm[tid] = sum * (1.f / 65536.f);
        __syncthreads();
        float acc2 = sbias[c];
#pragma unroll
        for (int k = 0; k < 32; k++)
            acc2 += sw[c * 32 + k] * mean_sm[bb * 32 + k];
        g_s[tid] = acc2;
    }
}

// =====================================================================
// K4: x*s -> conv3 -> y = inp + beta*x -> LN2 -> conv4 -> gate -> conv5
//     -> out. PIXEL-PAIR with psum2 epilogues (frozen from R15).
// =====================================================================
__global__ __launch_bounds__(128) void k4(const float* __restrict__ inp,
                                          const float* __restrict__ w3,
                                          const float* __restrict__ b3g,
                                          const float* __restrict__ w4,
                                          const float* __restrict__ b4g,
                                          const float* __restrict__ w5,
                                          const float* __restrict__ b5g,
                                          const float* __restrict__ n2wg,
                                          const float* __restrict__ n2bg,
                                          const float* __restrict__ betag,
                                          const float* __restrict__ gammag,
                                          float* __restrict__ out) {
    __shared__ __align__(16) __half2 w3h[32 * 16];  // [o][c2] channel pairs
    __shared__ __align__(16) __half2 w4h[64 * 16];
    __shared__ __align__(16) __half2 w5h[32 * 16];
    __shared__ __half2 b4ab[16], b4cd[16];  // (b4[2j],b4[2j+1]) / (+32,+33)
    __shared__ float sv[32], n2w[32], n2b[32], bet[32], gam[32];
    __shared__ float b3s[32], b5s[32];

    int tid = threadIdx.x;
    int p = blockIdx.x * 256 + tid * 2;  // 2 pixels per thread
    int b = p >> 16, pix = p & 65535;

    for (int i = tid; i < 512; i += 128) {
        int o = i >> 4, c2 = i & 15;
        w3h[i] = __floats2half2_rn(w3[o * 32 + 2 * c2], w3[o * 32 + 2 * c2 + 1]);
        w5h[i] = __floats2half2_rn(w5[o * 32 + 2 * c2], w5[o * 32 + 2 * c2 + 1]);
    }
    for (int i = tid; i < 1024; i += 128) {
        int o = i >> 4, c2 = i & 15;
        w4h[i] = __floats2half2_rn(w4[o * 32 + 2 * c2], w4[o * 32 + 2 * c2 + 1]);
    }
    if (tid < 32) {
        sv[tid] = g_s[b * 32 + tid];
        n2w[tid] = n2wg[tid];
        n2b[tid] = n2bg[tid];
        bet[tid] = betag[tid];
        gam[tid] = gammag[tid];
        b3s[tid] = b3g[tid];
        b5s[tid] = b5g[tid];
    }
    if (tid < 16) {
        b4ab[tid] = __floats2half2_rn(b4g[2 * tid], b4g[2 * tid + 1]);
        b4cd[tid] = __floats2half2_rn(b4g[2 * tid + 32], b4g[2 * tid + 33]);
    }
    __syncthreads();

    // x = gate_out * s (fp16 half2 loads: lanes = pixels); repack to
    // channel-paired half2 per pixel.
    __half2 xh0[16], xh1[16];
    {
        const __half* xg = g_xsg + b * CC * HW + pix;
#pragma unroll
        for (int c2 = 0; c2 < 16; c2++) {
            float2 fa = __half22float2(*(const __half2*)&xg[(2 * c2) * HW]);
            float2 fb = __half22float2(*(const __half2*)&xg[(2 * c2 + 1) * HW]);
            float s0 = sv[2 * c2], s1 = sv[2 * c2 + 1];
            xh0[c2] = __floats2half2_rn(fa.x * s0, fb.x * s1);  // pixel 0
            xh1[c2] = __floats2half2_rn(fa.y * s0, fb.y * s1);  // pixel 1
        }
    }

    // ---- conv3 (HFMA2, weights shared across pixels) + residual ----
    u64 yp0[16], yp1[16];  // channel pairs per pixel (fp32)
    const float* ip = inp + b * CC * HW + pix;
#pragma unroll 2
    for (int j = 0; j < 16; j++) {
        __half2 z = __floats2half2_rn(0.f, 0.f);
        __half2 a00 = z, a10 = z, a01 = z, a11 = z;
        const __half2* wr0 = &w3h[(2 * j) * 16];
        const __half2* wr1 = &w3h[(2 * j + 1) * 16];
#pragma unroll
        for (int c2 = 0; c2 < 16; c2++) {
            __half2 w0 = wr0[c2], w1 = wr1[c2];
            a00 = __hfma2(w0, xh0[c2], a00);
            a01 = __hfma2(w0, xh1[c2], a01);
            a10 = __hfma2(w1, xh0[c2], a10);
            a11 = __hfma2(w1, xh1[c2], a11);
        }
        float2 f0s = __half22float2(psum2(a00, a10));  // (sum ch2j, ch2j+1) p0
        float2 f1s = __half22float2(psum2(a01, a11));  // pixel 1
        float2 i0 = *(const float2*)&ip[(2 * j) * HW];  // (p0,p1)
        float2 i1 = *(const float2*)&ip[(2 * j + 1) * HW];
        float bt0 = bet[2 * j], bt1 = bet[2 * j + 1];
        float bb0 = b3s[2 * j], bb1 = b3s[2 * j + 1];
        yp0[j] = pack2(i0.x + bt0 * (bb0 + f0s.x), i1.x + bt1 * (bb1 + f0s.y));
        yp1[j] = pack2(i0.y + bt0 * (bb0 + f1s.x), i1.y + bt1 * (bb1 + f1s.y));
    }

    // ---- LN2 per pixel -> zh (reuse xh regs) ----
    {
        u64 sa0 = 0ull, qa0 = 0ull, sa1 = 0ull, qa1 = 0ull;
#pragma unroll
        for (int j = 0; j < 16; j++) {
            sa0 = add2(sa0, yp0[j]);
            qa0 = ffma2(yp0[j], yp0[j], qa0);
            sa1 = add2(sa1, yp1[j]);
            qa1 = ffma2(yp1[j], yp1[j], qa1);
        }
        float s0 = hsum2(sa0), q0 = hsum2(qa0);
        float s1 = hsum2(sa1), q1 = hsum2(qa1);
        float mu0 = s0 * (1.f / 32.f);
        float mu1 = s1 * (1.f / 32.f);
        float rstd0 = rsqrtf(q0 * (1.f / 32.f) - mu0 * mu0 + 1e-6f);
        float rstd1 = rsqrtf(q1 * (1.f / 32.f) - mu1 * mu1 + 1e-6f);
#pragma unroll
        for (int j = 0; j < 16; j++) {
            float w0 = n2w[2 * j], w1 = n2w[2 * j + 1];
            float c0 = n2b[2 * j], c1 = n2b[2 * j + 1];
            float2 f0 = unpack2(yp0[j]);
            float2 f1 = unpack2(yp1[j]);
            xh0[j] = __floats2half2_rn((f0.x - mu0) * rstd0 * w0 + c0,
                                       (f0.y - mu0) * rstd0 * w1 + c1);
            xh1[j] = __floats2half2_rn((f1.x - mu1) * rstd1 * w0 + c0,
                                       (f1.y - mu1) * rstd1 * w1 + c1);
        }
    }

    // ---- conv4 (64 outs, HFMA2, shared weights) + gate fully in half2 ----
    __half2 gh0[16], gh1[16];
#pragma unroll 2
    for (int j = 0; j < 16; j++) {
        __half2 z = __floats2half2_rn(0.f, 0.f);
        __half2 aA0 = z, aB0 = z, aC0 = z, aD0 = z;
        __half2 aA1 = z, aB1 = z, aC1 = z, aD1 = z;
        const __half2* wA = &w4h[(2 * j) * 16];
        const __half2* wB = &w4h[(2 * j + 1) * 16];
        const __half2* wC = &w4h[(2 * j + 32) * 16];
        const __half2* wD = &w4h[(2 * j + 33) * 16];
#pragma unroll
        for (int c2 = 0; c2 < 16; c2++) {
            __half2 x0 = xh0[c2], x1 = xh1[c2];
            __half2 wa = wA[c2], wb = wB[c2], wc = wC[c2], wd = wD[c2];
            aA0 = __hfma2(wa, x0, aA0);
            aA1 = __hfma2(wa, x1, aA1);
            aB0 = __hfma2(wb, x0, aB0);
            aB1 = __hfma2(wb, x1, aB1);
            aC0 = __hfma2(wc, x0, aC0);
            aC1 = __hfma2(wc, x1, aC1);
            aD0 = __hfma2(wd, x0, aD0);
            aD1 = __hfma2(wd, x1, aD1);
        }
        __half2 bab = b4ab[j], bcd = b4cd[j];
        gh0[j] = __hmul2(__hadd2(bab, psum2(aA0, aB0)),
                         __hadd2(bcd, psum2(aC0, aD0)));
        gh1[j] = __hmul2(__hadd2(bab, psum2(aA1, aB1)),
                         __hadd2(bcd, psum2(aC1, aD1)));
    }

    // ---- conv5 (HFMA2, shared weights) + final residual ----
    float* op = out + b * CC * HW + pix;
#pragma unroll 2
    for (int j = 0; j < 16; j++) {
        __half2 z = __floats2half2_rn(0.f, 0.f);
        __half2 a00 = z, a10 = z, a01 = z, a11 = z;
        const __half2* wr0 = &w5h[(2 * j) * 16];
        const __half2* wr1 = &w5h[(2 * j + 1) * 16];
#pragma unroll
        for (int c2 = 0; c2 < 16; c2++) {
            __half2 w0 = wr0[c2], w1 = wr1[c2];
            a00 = __hfma2(w0, gh0[c2], a00);
            a01 = __hfma2(w0, gh1[c2], a01);
            a10 = __hfma2(w1, gh0[c2], a10);
            a11 = __hfma2(w1, gh1[c2], a11);
        }
        float2 f0s = __half22float2(psum2(a00, a10));  // pixel 0 sums
        float2 f1s = __half22float2(psum2(a01, a11));  // pixel 1 sums
        float gm0 = gam[2 * j], gm1 = gam[2 * j + 1];
        float bb0 = b5s[2 * j], bb1 = b5s[2 * j + 1];
        float2 f0 = unpack2(yp0[j]);  // (ch even, ch odd) pixel 0
        float2 f1 = unpack2(yp1[j]);  // pixel 1
        *(float2*)&op[(2 * j) * HW] =
            make_float2(f0.x + gm0 * (bb0 + f0s.x), f1.x + gm0 * (bb0 + f1s.x));
        *(float2*)&op[(2 * j + 1) * HW] =
            make_float2(f0.y + gm1 * (bb1 + f0s.y), f1.y + gm1 * (bb1 + f1s.y));
    }
}

extern "C" void kernel_launch(void* const* d_in, const int* in_sizes, int n_in,
                              void* d_out, int out_size) {
    const float* inp     = (const float*)d_in[0];
    const float* w2      = (const float*)d_in[1];
    const float* conv1_w = (const float*)d_in[2];
    const float* conv1_b = (const float*)d_in[3];
    const float* conv3_w = (const float*)d_in[4];
    const float* conv3_b = (const float*)d_in[5];
    const float* sca_w   = (const float*)d_in[6];
    const float* sca_b   = (const float*)d_in[7];
    const float* conv4_w = (const float*)d_in[8];
    const float* conv4_b = (const float*)d_in[9];
    const float* conv5_w = (const float*)d_in[10];
    const float* conv5_b = (const float*)d_in[11];
    const float* norm1_w = (const float*)d_in[12];
    const float* norm1_b = (const float*)d_in[13];
    const float* norm2_w = (const float*)d_in[14];
    const float* norm2_b = (const float*)d_in[15];
    const float* beta    = (const float*)d_in[16];
    const float* gamma   = (const float*)d_in[17];
    float* out = (float*)d_out;

    k1<<<1024, 128>>>(inp, conv1_w, conv1_b, norm1_w, norm1_b);
    k2<<<dim3(64, 32, 4), 128>>>(w2, sca_w, sca_b);
    k4<<<1024, 128>>>(inp, conv3_w, conv3_b, conv4_w, conv4_b, conv5_w, conv5_b,
                      norm2_w, norm2_b, beta, gamma, out);
}